// round 11
// baseline (speedup 1.0000x reference)
#include <cuda_runtime.h>
#include <cuda_bf16.h>
#include <cuda_fp16.h>
#include <math.h>

#define NN 50000
#define EE 400000
#define GG 256
#define HH 256
#define NDEPTH 6

// ---------------- scratch (device globals) -----------------------------------
__device__ __half d_hn[NN * HH];               // fp16 h (gather input, low-precision)
__device__ unsigned d_hres[NN * HH];           // packed bf16x2 residual state (accurate)
__device__ __nv_bfloat16 d_s_hi[NN * HH];      // gathered sum hi limb (GEMM A)
__device__ __nv_bfloat16 d_s_lo[NN * HH];      // gathered sum lo limb
__device__ float d_s0[NN * 48];                // layer-0 gathered feats/edge means
__device__ __nv_bfloat16 d_whi[12 * HH * HH];  // weights transposed [n][k], hi
__device__ __nv_bfloat16 d_wlo[12 * HH * HH];  // weights transposed [n][k], lo
__device__ int   d_deg_in[NN];
__device__ int   d_deg_out[NN];
__device__ int   d_cursor[NN];
__device__ int   d_rowptr[NN + 1];
__device__ int   d_eid[EE];
__device__ int   d_esrc[EE];
__device__ float d_norm_o[NN];
__device__ float d_norm_i[NN];
__device__ float d_pooled[GG * HH];
__device__ int   d_cnt[GG];

// ---------------- helpers -----------------------------------------------------
__device__ __forceinline__ float block_sum_256(float v, float* red) {
  #pragma unroll
  for (int o = 16; o > 0; o >>= 1) v += __shfl_down_sync(0xffffffffu, v, o);
  int lane = threadIdx.x & 31, w = threadIdx.x >> 5;
  if (lane == 0) red[w] = v;
  __syncthreads();
  if (threadIdx.x < 8) {
    float x = red[threadIdx.x];
    #pragma unroll
    for (int o = 4; o > 0; o >>= 1) x += __shfl_down_sync(0xffu, x, o);
    if (threadIdx.x == 0) red[0] = x;
  }
  __syncthreads();
  float r = red[0];
  __syncthreads();
  return r;
}

__device__ __forceinline__ float up2(unsigned u) {
  return __uint_as_float(u << 16) + __uint_as_float(u & 0xffff0000u);
}
__device__ __forceinline__ unsigned pk2(float x) {
  unsigned short h = __bfloat16_as_ushort(__float2bfloat16(x));
  float hf = __uint_as_float(((unsigned)h) << 16);
  unsigned short l = __bfloat16_as_ushort(__float2bfloat16(x - hf));
  return (unsigned)h | (((unsigned)l) << 16);
}

__device__ __forceinline__ void mma_bf16(float* c, const unsigned* a, const unsigned* b) {
  asm volatile(
      "mma.sync.aligned.m16n8k16.row.col.f32.bf16.bf16.f32 "
      "{%0,%1,%2,%3}, {%4,%5,%6,%7}, {%8,%9}, {%0,%1,%2,%3};\n"
      : "+f"(c[0]), "+f"(c[1]), "+f"(c[2]), "+f"(c[3])
      : "r"(a[0]), "r"(a[1]), "r"(a[2]), "r"(a[3]), "r"(b[0]), "r"(b[1]));
}

__device__ __forceinline__ void ldsm4(unsigned* r, unsigned saddr) {
  asm volatile("ldmatrix.sync.aligned.m8n8.x4.shared.b16 {%0,%1,%2,%3}, [%4];"
               : "=r"(r[0]), "=r"(r[1]), "=r"(r[2]), "=r"(r[3]) : "r"(saddr));
}

__device__ __forceinline__ void cpa16(unsigned saddr, const void* gaddr, bool pred) {
  int sz = pred ? 16 : 0;
  asm volatile("cp.async.cg.shared.global [%0], [%1], 16, %2;\n"
               :: "r"(saddr), "l"(gaddr), "r"(sz));
}
__device__ __forceinline__ void cpa_commit() {
  asm volatile("cp.async.commit_group;\n");
}
template <int N>
__device__ __forceinline__ void cpa_wait() {
  asm volatile("cp.async.wait_group %0;\n" :: "n"(N));
}

// ---------------- preprocessing -----------------------------------------------
__global__ void k_zero() {
  int i = blockIdx.x * blockDim.x + threadIdx.x;
  if (i < NN) { d_deg_in[i] = 0; d_deg_out[i] = 0; d_cursor[i] = 0; }
  if (i < GG * HH) d_pooled[i] = 0.f;
  if (i < GG) d_cnt[i] = 0;
}

__global__ void k_hist(const int* __restrict__ src, const int* __restrict__ dst) {
  int e = blockIdx.x * blockDim.x + threadIdx.x;
  if (e < EE) {
    atomicAdd(&d_deg_in[dst[e]], 1);
    atomicAdd(&d_deg_out[src[e]], 1);
  }
}

__global__ void k_scan() {
  __shared__ int warp_tot[32];
  __shared__ int s_carry;
  int t = threadIdx.x, lane = t & 31, w = t >> 5;
  if (t == 0) s_carry = 0;
  __syncthreads();
  for (int base = 0; base < NN; base += 1024) {
    int v = (base + t < NN) ? d_deg_in[base + t] : 0;
    int x = v;
    #pragma unroll
    for (int o = 1; o < 32; o <<= 1) {
      int y = __shfl_up_sync(0xffffffffu, x, o);
      if (lane >= o) x += y;
    }
    if (lane == 31) warp_tot[w] = x;
    __syncthreads();
    if (w == 0) {
      int y = warp_tot[lane];
      int z = y;
      #pragma unroll
      for (int o = 1; o < 32; o <<= 1) {
        int q = __shfl_up_sync(0xffffffffu, z, o);
        if (lane >= o) z += q;
      }
      warp_tot[lane] = z - y;
    }
    __syncthreads();
    int incl = x + warp_tot[w];
    int carry = s_carry;
    if (base + t < NN) d_rowptr[base + t] = carry + incl - v;
    __syncthreads();
    if (t == 1023) s_carry = carry + incl;
    __syncthreads();
  }
  if (threadIdx.x == 0) d_rowptr[NN] = s_carry;
}

__global__ void k_fill(const int* __restrict__ src, const int* __restrict__ dst) {
  int e = blockIdx.x * blockDim.x + threadIdx.x;
  if (e < EE) {
    int dnode = dst[e];
    int pos = atomicAdd(&d_cursor[dnode], 1);
    int idx = d_rowptr[dnode] + pos;
    d_eid[idx] = e;
    d_esrc[idx] = src[e];
  }
}

__global__ void k_norms() {
  int i = blockIdx.x * blockDim.x + threadIdx.x;
  if (i < NN) {
    int di = d_deg_in[i];
    int dq = d_deg_out[i];
    d_norm_i[i] = (di > 0) ? rsqrtf((float)di) : 0.f;
    d_norm_o[i] = (dq > 0) ? rsqrtf((float)dq) : 0.f;
  }
}

// split + transpose all 12 weight matrices into bf16 hi/lo [n][k]
__global__ void k_wsplit(const float* __restrict__ Wc1, const float* __restrict__ Wc2) {
  int i = blockIdx.x * blockDim.x + threadIdx.x;
  if (i >= 12 * 65536) return;
  int slot = i >> 16, r = i & 65535;
  int k = r >> 8, n = r & 255;
  float w = (slot < 6) ? Wc1[(size_t)slot * 65536 + k * 256 + n]
                       : Wc2[(size_t)(slot - 6) * 65536 + k * 256 + n];
  __nv_bfloat16 hi = __float2bfloat16(w);
  size_t dstix = (size_t)slot * 65536 + n * 256 + k;
  d_whi[dstix] = hi;
  d_wlo[dstix] = __float2bfloat16(w - __bfloat162float(hi));
}

// ---------------- layer-0 gather ------------------------------------------------
__global__ void __launch_bounds__(256) k_gather0(
    const float* __restrict__ a_t, const float* __restrict__ c_t,
    const float* __restrict__ x_t, const float* __restrict__ e_t) {
  int wid = threadIdx.x >> 5, l = threadIdx.x & 31;
  int n = blockIdx.x * 8 + wid;
  if (n >= NN) return;
  int beg = d_rowptr[n], end = d_rowptr[n + 1];
  float accf = 0.f, acce = 0.f;
  for (int p = beg; p < end; p++) {
    int eid = d_eid[p];
    int s = d_esrc[p];
    float no = d_norm_o[s];
    float f = 0.f;
    if (l < 16) f = a_t[s * 16 + l];
    else if (l < 24) f = c_t[s * 8 + (l - 16)];
    else if (l < 27) f = x_t[s * 3 + (l - 24)];
    accf += f * no;
    if (l < 16) acce += e_t[(size_t)eid * 16 + l];
  }
  int deg = end - beg;
  if (l < 27) d_s0[n * 48 + l] = accf * d_norm_i[n];
  if (l < 16) d_s0[n * 48 + 32 + l] = acce / (float)max(deg, 1);
}

// ---------------- layer 0 (writes fp16 h into d_hn, bf16x2 into d_hres) ---------
__global__ void __launch_bounds__(256) k_layer0(
    const float* __restrict__ W_in, const float* __restrict__ b_in,
    const float* __restrict__ W_e, const float* __restrict__ b_e) {
  __shared__ float st[16][48];
  int j = threadIdx.x;
  int node0 = blockIdx.x * 16;
  float wf[27], we[16];
  #pragma unroll
  for (int k = 0; k < 27; k++) wf[k] = W_in[k * 256 + j];
  #pragma unroll
  for (int k = 0; k < 16; k++) we[k] = W_e[k * 256 + j];
  for (int q = j; q < 16 * 48; q += 256) {
    int r = q / 48, c = q % 48;
    int nd = node0 + r;
    st[r][c] = (nd < NN) ? d_s0[nd * 48 + c] : 0.f;
  }
  __syncthreads();
  float bi = b_in[j], be = b_e[j];
  for (int rr = 0; rr < 16; rr++) {
    int nd = node0 + rr;
    if (nd >= NN) break;
    float v = bi;
    #pragma unroll
    for (int k = 0; k < 27; k++) v += wf[k] * st[rr][k];
    if (d_deg_in[nd] > 0) {
      float e = be;
      #pragma unroll
      for (int k = 0; k < 16; k++) e += we[k] * st[rr][32 + k];
      v += e;
    }
    size_t ix = (size_t)nd * 256 + j;
    d_hn[ix] = __float2half_rn(v);
    d_hres[ix] = pk2(v);
  }
}

// ---------------- gather: s = norm_i * sum(norm_o[src] * fp16 hn[src]) ----------
// warp per dst node, lane covers 8 contiguous columns (one uint4 per row).
__global__ void __launch_bounds__(256) k_gather() {
  __shared__ int ssrc[8][128];
  int wid = threadIdx.x >> 5, l = threadIdx.x & 31;
  int n = blockIdx.x * 8 + wid;
  if (n >= NN) return;
  int beg = d_rowptr[n], end = d_rowptr[n + 1];
  const int gc = l * 8;
  float acc[8];
  #pragma unroll
  for (int c = 0; c < 8; c++) acc[c] = 0.f;
  for (int base = beg; base < end; base += 128) {
    int cnt = min(128, end - base);
    for (int i = l; i < cnt; i += 32) ssrc[wid][i] = d_esrc[base + i];
    __syncwarp();
    int e = 0;
    for (; e + 2 <= cnt; e += 2) {
      int s0 = ssrc[wid][e], s1 = ssrc[wid][e + 1];
      float n0 = d_norm_o[s0], n1 = d_norm_o[s1];
      uint4 a0 = *(const uint4*)(d_hn + (size_t)s0 * 256 + gc);
      uint4 a1 = *(const uint4*)(d_hn + (size_t)s1 * 256 + gc);
      const __half2* p0 = (const __half2*)&a0;
      const __half2* p1 = (const __half2*)&a1;
      #pragma unroll
      for (int c = 0; c < 4; c++) {
        float2 f0 = __half22float2(p0[c]);
        float2 f1 = __half22float2(p1[c]);
        acc[2 * c]     += f0.x * n0 + f1.x * n1;
        acc[2 * c + 1] += f0.y * n0 + f1.y * n1;
      }
    }
    if (e < cnt) {
      int s0 = ssrc[wid][e];
      float n0 = d_norm_o[s0];
      uint4 a0 = *(const uint4*)(d_hn + (size_t)s0 * 256 + gc);
      const __half2* p0 = (const __half2*)&a0;
      #pragma unroll
      for (int c = 0; c < 4; c++) {
        float2 f0 = __half22float2(p0[c]);
        acc[2 * c]     += f0.x * n0;
        acc[2 * c + 1] += f0.y * n0;
      }
    }
    __syncwarp();
  }
  float ni = d_norm_i[n];
  unsigned short hs[8], ls[8];
  #pragma unroll
  for (int c = 0; c < 8; c++) {
    float v = acc[c] * ni;
    hs[c] = __bfloat16_as_ushort(__float2bfloat16(v));
    float hf = __uint_as_float(((unsigned)hs[c]) << 16);
    ls[c] = __bfloat16_as_ushort(__float2bfloat16(v - hf));
  }
  size_t ox = (size_t)n * 256 + gc;
  uint4 hv, lv;
  hv.x = (unsigned)hs[0] | ((unsigned)hs[1] << 16);
  hv.y = (unsigned)hs[2] | ((unsigned)hs[3] << 16);
  hv.z = (unsigned)hs[4] | ((unsigned)hs[5] << 16);
  hv.w = (unsigned)hs[6] | ((unsigned)hs[7] << 16);
  lv.x = (unsigned)ls[0] | ((unsigned)ls[1] << 16);
  lv.y = (unsigned)ls[2] | ((unsigned)ls[3] << 16);
  lv.z = (unsigned)ls[4] | ((unsigned)ls[5] << 16);
  lv.w = (unsigned)ls[6] | ((unsigned)ls[7] << 16);
  *(uint4*)(d_s_hi + ox) = hv;
  *(uint4*)(d_s_lo + ox) = lv;
}

// ---------------- fused GEMM + bias + LN + SiLU + resid + pack ------------------
// block = 64 rows x N=256, 256 threads (8 warps: 2m x 4n), warp tile 32x64.
// smem 100352B. BK=16, 2-stage B ring. B rows 32B with XOR-16 swizzle.
#define A_ROW 528                          // 512B data + 16 pad
#define A_LIMB (64 * A_ROW)                // 33792
#define B_OFF (2 * A_LIMB)                 // 67584
#define B_LROW 32
#define B_LIMB (256 * B_LROW)              // 8192
#define B_STG (2 * B_LIMB)                 // 16384
#define FUSED_SMEM (B_OFF + 2 * B_STG)     // 100352 bytes

extern __shared__ __align__(16) unsigned char g_sm[];

__global__ void __launch_bounds__(256, 2) k_fused(
    int wslot, const float* __restrict__ bias, const float* __restrict__ gamma,
    const float* __restrict__ beta, int resid) {
  const __nv_bfloat16* wh = d_whi + (size_t)wslot * 65536;
  const __nv_bfloat16* wl = d_wlo + (size_t)wslot * 65536;

  const int t = threadIdx.x;
  const int lane = t & 31;
  const int wid = t >> 5;
  const int wm = wid & 1;       // 0..1 (m)
  const int wn = wid >> 1;      // 0..3 (n)
  const int fr = lane >> 2;
  const int fc = lane & 3;
  const int bm = blockIdx.x * 64;
  const int sel = lane >> 3;
  const int lr = lane & 7;

  unsigned sbase = (unsigned)__cvta_generic_to_shared((void*)g_sm);

  // ---- A dense load: 2 limbs x 64 rows x 32 chunks (16B), zfill OOB rows ----
  #pragma unroll
  for (int i = 0; i < 16; i++) {
    int q = t + 256 * i;
    int limb = q >> 11;
    int r = (q >> 5) & 63;
    int c = q & 31;
    int gr = bm + r;
    bool ok = gr < NN;
    const __nv_bfloat16* srcp = limb ? d_s_lo : d_s_hi;
    cpa16(sbase + limb * A_LIMB + r * A_ROW + c * 16,
          srcp + (size_t)(ok ? gr : 0) * 256 + c * 8, ok);
  }

  // ---- B stage loader (swizzled 32B rows) ----
  auto load_b = [&](int st, int k0) {
    unsigned sb = sbase + B_OFF + st * B_STG;
    #pragma unroll
    for (int i2 = 0; i2 < 2; i2++) {
      int q = t + 256 * i2;             // 512: 256 rows x 2 chunks
      int row = q >> 1, c = q & 1;
      unsigned off = row * B_LROW + ((c ^ ((row >> 2) & 1)) << 4);
      size_t go = (size_t)row * 256 + k0 + c * 8;
      cpa16(sb + off, wh + go, true);
      cpa16(sb + B_LIMB + off, wl + go, true);
    }
    cpa_commit();
  };
  load_b(0, 0);     // commits A + B0 together
  load_b(1, 16);

  // ---- MMA mainloop (16 K16 slabs) ----
  float acc[2][8][4];
  #pragma unroll
  for (int i = 0; i < 2; i++)
    #pragma unroll
    for (int j = 0; j < 8; j++)
      #pragma unroll
      for (int q = 0; q < 4; q++) acc[i][j][q] = 0.f;

  const int a_row = (sel & 1) * 8 + lr;
  const int a_kad = (sel >> 1) * 8;
  const int b_row = (sel >> 1) * 8 + lr;
  const int b_kc  = sel & 1;

  #pragma unroll 1
  for (int s = 0; s < 16; s++) {
    if (s == 15) cpa_wait<0>(); else cpa_wait<1>();
    __syncthreads();
    unsigned sb = sbase + B_OFF + (s & 1) * B_STG;
    const int ka = s * 16;

    unsigned af[2][2][4];
    #pragma unroll
    for (int i = 0; i < 2; i++) {
      int row = wm * 32 + i * 16 + a_row;
      #pragma unroll
      for (int L = 0; L < 2; L++)
        ldsm4(af[i][L], sbase + L * A_LIMB + row * A_ROW + (ka + a_kad) * 2);
    }
    unsigned bf[4][4];
    // B hi
    #pragma unroll
    for (int g = 0; g < 4; g++) {
      int nrow = wn * 64 + g * 16 + b_row;
      ldsm4(bf[g], sb + nrow * B_LROW + ((b_kc ^ ((nrow >> 2) & 1)) << 4));
    }
    #pragma unroll
    for (int i = 0; i < 2; i++)
      #pragma unroll
      for (int g = 0; g < 4; g++) {
        mma_bf16(acc[i][2 * g],     af[i][0], bf[g]);
        mma_bf16(acc[i][2 * g + 1], af[i][0], bf[g] + 2);
        mma_bf16(acc[i][2 * g],     af[i][1], bf[g]);
        mma_bf16(acc[i][2 * g + 1], af[i][1], bf[g] + 2);
      }
    // B lo (x A hi)
    #pragma unroll
    for (int g = 0; g < 4; g++) {
      int nrow = wn * 64 + g * 16 + b_row;
      ldsm4(bf[g], sb + B_LIMB + nrow * B_LROW + ((b_kc ^ ((nrow >> 2) & 1)) << 4));
    }
    #pragma unroll
    for (int i = 0; i < 2; i++)
      #pragma unroll
      for (int g = 0; g < 4; g++) {
        mma_bf16(acc[i][2 * g],     af[i][0], bf[g]);
        mma_bf16(acc[i][2 * g + 1], af[i][0], bf[g] + 2);
      }
    __syncthreads();
    if (s + 2 < 16) load_b(s & 1, (s + 2) * 16);
  }

  // ---- epilogue: bias -> LN -> SiLU -> resid -> pack ----
  __syncthreads();
  float* epi = (float*)g_sm;
  float* psum = epi;              // [64][4]
  float* psq  = epi + 256;        // [64][4]
  float* pmu  = epi + 512;        // [64]
  float* prs  = epi + 576;        // [64]

  #pragma unroll
  for (int j = 0; j < 8; j++) {
    int c0 = wn * 64 + j * 8 + 2 * fc;
    float b0 = bias[c0], b1 = bias[c0 + 1];
    #pragma unroll
    for (int i = 0; i < 2; i++) {
      acc[i][j][0] += b0; acc[i][j][1] += b1;
      acc[i][j][2] += b0; acc[i][j][3] += b1;
    }
  }

  #pragma unroll
  for (int i = 0; i < 2; i++) {
    float s0 = 0.f, q0 = 0.f, s1 = 0.f, q1 = 0.f;
    #pragma unroll
    for (int j = 0; j < 8; j++) {
      s0 += acc[i][j][0] + acc[i][j][1];
      q0 += acc[i][j][0] * acc[i][j][0] + acc[i][j][1] * acc[i][j][1];
      s1 += acc[i][j][2] + acc[i][j][3];
      q1 += acc[i][j][2] * acc[i][j][2] + acc[i][j][3] * acc[i][j][3];
    }
    #pragma unroll
    for (int o = 1; o <= 2; o <<= 1) {
      s0 += __shfl_xor_sync(0xffffffffu, s0, o);
      q0 += __shfl_xor_sync(0xffffffffu, q0, o);
      s1 += __shfl_xor_sync(0xffffffffu, s1, o);
      q1 += __shfl_xor_sync(0xffffffffu, q1, o);
    }
    if (fc == 0) {
      int r0 = wm * 32 + i * 16 + fr;
      psum[r0 * 4 + wn] = s0; psq[r0 * 4 + wn] = q0;
      psum[(r0 + 8) * 4 + wn] = s1; psq[(r0 + 8) * 4 + wn] = q1;
    }
  }
  __syncthreads();
  if (t < 64) {
    float s = psum[t * 4] + psum[t * 4 + 1] + psum[t * 4 + 2] + psum[t * 4 + 3];
    float q = psq[t * 4] + psq[t * 4 + 1] + psq[t * 4 + 2] + psq[t * 4 + 3];
    float mu = s * (1.f / 256.f);
    float var = q * (1.f / 256.f) - mu * mu;
    pmu[t] = mu;
    prs[t] = rsqrtf(var + 1e-5f);
  }
  __syncthreads();

  #pragma unroll
  for (int i = 0; i < 2; i++) {
    int r0l = wm * 32 + i * 16 + fr;
    int r1l = r0l + 8;
    int gr0 = bm + r0l, gr1 = bm + r1l;
    float mu0 = pmu[r0l], rs0 = prs[r0l];
    float mu1 = pmu[r1l], rs1 = prs[r1l];
    #pragma unroll
    for (int j = 0; j < 8; j++) {
      int c0 = wn * 64 + j * 8 + 2 * fc;
      float ga0 = gamma[c0], ga1 = gamma[c0 + 1];
      float be0 = beta[c0], be1 = beta[c0 + 1];
      float y0 = (acc[i][j][0] - mu0) * rs0 * ga0 + be0;
      float y1 = (acc[i][j][1] - mu0) * rs0 * ga1 + be1;
      float y2 = (acc[i][j][2] - mu1) * rs1 * ga0 + be0;
      float y3 = (acc[i][j][3] - mu1) * rs1 * ga1 + be1;
      y0 = y0 / (1.f + __expf(-y0));
      y1 = y1 / (1.f + __expf(-y1));
      y2 = y2 / (1.f + __expf(-y2));
      y3 = y3 / (1.f + __expf(-y3));
      if (gr0 < NN) {
        size_t ix = (size_t)gr0 * 256 + c0;
        if (resid) {
          uint2 old = *(uint2*)(d_hres + ix);
          y0 += up2(old.x); y1 += up2(old.y);
          uint2 pv; pv.x = pk2(y0); pv.y = pk2(y1);
          *(uint2*)(d_hres + ix) = pv;
        }
        *(__half2*)(d_hn + ix) = __floats2half2_rn(y0, y1);
      }
      if (gr1 < NN) {
        size_t ix = (size_t)gr1 * 256 + c0;
        if (resid) {
          uint2 old = *(uint2*)(d_hres + ix);
          y2 += up2(old.x); y3 += up2(old.y);
          uint2 pv; pv.x = pk2(y2); pv.y = pk2(y3);
          *(uint2*)(d_hres + ix) = pv;
        }
        *(__half2*)(d_hn + ix) = __floats2half2_rn(y2, y3);
      }
    }
  }
}

// ---------------- pooling + head ------------------------------------------------
__global__ void k_pool(const int* __restrict__ gid) {
  int n = blockIdx.x, j = threadIdx.x;
  int g = gid[n];
  atomicAdd(&d_pooled[g * HH + j], up2(d_hres[(size_t)n * HH + j]));
  if (j == 0) atomicAdd(&d_cnt[g], 1);
}

__global__ void k_head(const float* __restrict__ W_head,
                       const float* __restrict__ b_head,
                       float* __restrict__ out) {
  __shared__ float red[8];
  int g = blockIdx.x, j = threadIdx.x;
  float c = (float)d_cnt[g];
  float v = d_pooled[g * HH + j] / fmaxf(c, 1.f) * W_head[j];
  float s = block_sum_256(v, red);
  if (j == 0) {
    float x = s + b_head[0];
    out[g] = (x > 20.f) ? x : log1pf(expf(x));
  }
}

// ---------------- launcher ------------------------------------------------------
extern "C" void kernel_launch(void* const* d_in, const int* in_sizes, int n_in,
                              void* d_out, int out_size) {
  const float* a_t   = (const float*)d_in[0];
  const float* c_t   = (const float*)d_in[1];
  const float* x_t   = (const float*)d_in[2];
  const float* e_t   = (const float*)d_in[3];
  const int*   src   = (const int*)d_in[4];
  const int*   dst   = (const int*)d_in[5];
  const int*   gid   = (const int*)d_in[6];
  const float* W_in  = (const float*)d_in[7];
  const float* b_in  = (const float*)d_in[8];
  const float* W_e   = (const float*)d_in[9];
  const float* b_e   = (const float*)d_in[10];
  const float* Wc1   = (const float*)d_in[11];
  const float* bc1   = (const float*)d_in[12];
  const float* g1    = (const float*)d_in[13];
  const float* be1   = (const float*)d_in[14];
  const float* Wc2   = (const float*)d_in[15];
  const float* bc2   = (const float*)d_in[16];
  const float* g2    = (const float*)d_in[17];
  const float* be2   = (const float*)d_in[18];
  const float* W_hd  = (const float*)d_in[19];
  const float* b_hd  = (const float*)d_in[20];
  float* out = (float*)d_out;

  static bool attr_set = false;
  if (!attr_set) {
    cudaFuncSetAttribute(k_fused, cudaFuncAttributeMaxDynamicSharedMemorySize,
                         FUSED_SMEM);
    attr_set = true;
  }

  const int FGRID = (NN + 63) / 64;   // 782

  k_zero<<<(GG * HH + 255) / 256, 256>>>();
  k_hist<<<(EE + 255) / 256, 256>>>(src, dst);
  k_scan<<<1, 1024>>>();
  k_fill<<<(EE + 255) / 256, 256>>>(src, dst);
  k_norms<<<(NN + 255) / 256, 256>>>();
  k_wsplit<<<(12 * 65536 + 255) / 256, 256>>>(Wc1, Wc2);

  k_gather0<<<(NN + 7) / 8, 256>>>(a_t, c_t, x_t, e_t);
  k_layer0<<<(NN + 15) / 16, 256>>>(W_in, b_in, W_e, b_e);

  for (int l = 0; l < NDEPTH; l++) {
    k_gather<<<(NN + 7) / 8, 256>>>();
    k_fused<<<FGRID, 256, FUSED_SMEM>>>(l, bc1 + l * HH, g1 + l * HH,
                                        be1 + l * HH, 0);
    k_gather<<<(NN + 7) / 8, 256>>>();
    k_fused<<<FGRID, 256, FUSED_SMEM>>>(6 + l, bc2 + l * HH, g2 + l * HH,
                                        be2 + l * HH, 1);
  }

  k_pool<<<NN, 256>>>(gid);
  k_head<<<GG, 256>>>(W_hd, b_hd, out);
}

// round 12
// speedup vs baseline: 1.3043x; 1.3043x over previous
#include <cuda_runtime.h>
#include <cuda_bf16.h>
#include <math.h>

#define NN 50000
#define EE 400000
#define GG 256
#define HH 256
#define NDEPTH 6

// ---------------- scratch (device globals) -----------------------------------
__device__ unsigned d_hn[NN * HH];             // packed bf16x2 of h (gather input)
__device__ unsigned d_hres[NN * HH];           // packed bf16x2 residual state
__device__ __nv_bfloat16 d_s_hi[NN * HH];      // gathered sum hi limb (GEMM A)
__device__ __nv_bfloat16 d_s_lo[NN * HH];      // gathered sum lo limb
__device__ float d_s0[NN * 48];                // layer-0 gathered feats/edge means
__device__ __nv_bfloat16 d_whi[12 * HH * HH];  // weights transposed [n][k], hi
__device__ __nv_bfloat16 d_wlo[12 * HH * HH];  // weights transposed [n][k], lo
__device__ int   d_deg_in[NN];
__device__ int   d_deg_out[NN];
__device__ int   d_cursor[NN];
__device__ int   d_rowptr[NN + 1];
__device__ int   d_eid[EE];
__device__ int   d_esrc[EE];
__device__ float d_norm_o[NN];
__device__ float d_norm_i[NN];

// ---------------- helpers -----------------------------------------------------
__device__ __forceinline__ float block_sum_256(float v, float* red) {
  #pragma unroll
  for (int o = 16; o > 0; o >>= 1) v += __shfl_down_sync(0xffffffffu, v, o);
  int lane = threadIdx.x & 31, w = threadIdx.x >> 5;
  if (lane == 0) red[w] = v;
  __syncthreads();
  if (threadIdx.x < 8) {
    float x = red[threadIdx.x];
    #pragma unroll
    for (int o = 4; o > 0; o >>= 1) x += __shfl_down_sync(0xffu, x, o);
    if (threadIdx.x == 0) red[0] = x;
  }
  __syncthreads();
  float r = red[0];
  __syncthreads();
  return r;
}

__device__ __forceinline__ float up2(unsigned u) {
  return __uint_as_float(u << 16) + __uint_as_float(u & 0xffff0000u);
}
__device__ __forceinline__ unsigned pk2(float x) {
  unsigned short h = __bfloat16_as_ushort(__float2bfloat16(x));
  float hf = __uint_as_float(((unsigned)h) << 16);
  unsigned short l = __bfloat16_as_ushort(__float2bfloat16(x - hf));
  return (unsigned)h | (((unsigned)l) << 16);
}

__device__ __forceinline__ void mma_bf16(float* c, const unsigned* a, const unsigned* b) {
  asm volatile(
      "mma.sync.aligned.m16n8k16.row.col.f32.bf16.bf16.f32 "
      "{%0,%1,%2,%3}, {%4,%5,%6,%7}, {%8,%9}, {%0,%1,%2,%3};\n"
      : "+f"(c[0]), "+f"(c[1]), "+f"(c[2]), "+f"(c[3])
      : "r"(a[0]), "r"(a[1]), "r"(a[2]), "r"(a[3]), "r"(b[0]), "r"(b[1]));
}

__device__ __forceinline__ void ldsm4(unsigned* r, unsigned saddr) {
  asm volatile("ldmatrix.sync.aligned.m8n8.x4.shared.b16 {%0,%1,%2,%3}, [%4];"
               : "=r"(r[0]), "=r"(r[1]), "=r"(r[2]), "=r"(r[3]) : "r"(saddr));
}

__device__ __forceinline__ void cpa16(unsigned saddr, const void* gaddr, bool pred) {
  int sz = pred ? 16 : 0;
  asm volatile("cp.async.cg.shared.global [%0], [%1], 16, %2;\n"
               :: "r"(saddr), "l"(gaddr), "r"(sz));
}
__device__ __forceinline__ void cpa_commit() {
  asm volatile("cp.async.commit_group;\n");
}
template <int N>
__device__ __forceinline__ void cpa_wait() {
  asm volatile("cp.async.wait_group %0;\n" :: "n"(N));
}

// ---------------- preprocessing -----------------------------------------------
__global__ void k_zero() {
  int i = blockIdx.x * blockDim.x + threadIdx.x;
  if (i < NN) { d_deg_in[i] = 0; d_deg_out[i] = 0; d_cursor[i] = 0; }
}

__global__ void k_hist(const int* __restrict__ src, const int* __restrict__ dst) {
  int e = blockIdx.x * blockDim.x + threadIdx.x;
  if (e < EE) {
    atomicAdd(&d_deg_in[dst[e]], 1);
    atomicAdd(&d_deg_out[src[e]], 1);
  }
}

__global__ void k_scan() {
  __shared__ int warp_tot[32];
  __shared__ int s_carry;
  int t = threadIdx.x, lane = t & 31, w = t >> 5;
  if (t == 0) s_carry = 0;
  __syncthreads();
  for (int base = 0; base < NN; base += 1024) {
    int v = (base + t < NN) ? d_deg_in[base + t] : 0;
    int x = v;
    #pragma unroll
    for (int o = 1; o < 32; o <<= 1) {
      int y = __shfl_up_sync(0xffffffffu, x, o);
      if (lane >= o) x += y;
    }
    if (lane == 31) warp_tot[w] = x;
    __syncthreads();
    if (w == 0) {
      int y = warp_tot[lane];
      int z = y;
      #pragma unroll
      for (int o = 1; o < 32; o <<= 1) {
        int q = __shfl_up_sync(0xffffffffu, z, o);
        if (lane >= o) z += q;
      }
      warp_tot[lane] = z - y;
    }
    __syncthreads();
    int incl = x + warp_tot[w];
    int carry = s_carry;
    if (base + t < NN) d_rowptr[base + t] = carry + incl - v;
    __syncthreads();
    if (t == 1023) s_carry = carry + incl;
    __syncthreads();
  }
  if (threadIdx.x == 0) d_rowptr[NN] = s_carry;
}

__global__ void k_fill(const int* __restrict__ src, const int* __restrict__ dst) {
  int e = blockIdx.x * blockDim.x + threadIdx.x;
  if (e < EE) {
    int dnode = dst[e];
    int pos = atomicAdd(&d_cursor[dnode], 1);
    int idx = d_rowptr[dnode] + pos;
    d_eid[idx] = e;
    d_esrc[idx] = src[e];
  }
}

__global__ void k_norms() {
  int i = blockIdx.x * blockDim.x + threadIdx.x;
  if (i < NN) {
    int di = d_deg_in[i];
    int dq = d_deg_out[i];
    d_norm_i[i] = (di > 0) ? rsqrtf((float)di) : 0.f;
    d_norm_o[i] = (dq > 0) ? rsqrtf((float)dq) : 0.f;
  }
}

// split + transpose all 12 weight matrices into bf16 hi/lo [n][k]
__global__ void k_wsplit(const float* __restrict__ Wc1, const float* __restrict__ Wc2) {
  int i = blockIdx.x * blockDim.x + threadIdx.x;
  if (i >= 12 * 65536) return;
  int slot = i >> 16, r = i & 65535;
  int k = r >> 8, n = r & 255;
  float w = (slot < 6) ? Wc1[(size_t)slot * 65536 + k * 256 + n]
                       : Wc2[(size_t)(slot - 6) * 65536 + k * 256 + n];
  __nv_bfloat16 hi = __float2bfloat16(w);
  size_t dstix = (size_t)slot * 65536 + n * 256 + k;
  d_whi[dstix] = hi;
  d_wlo[dstix] = __float2bfloat16(w - __bfloat162float(hi));
}

// ---------------- layer-0 gather ------------------------------------------------
__global__ void __launch_bounds__(256) k_gather0(
    const float* __restrict__ a_t, const float* __restrict__ c_t,
    const float* __restrict__ x_t, const float* __restrict__ e_t) {
  int wid = threadIdx.x >> 5, l = threadIdx.x & 31;
  int n = blockIdx.x * 8 + wid;
  if (n >= NN) return;
  int beg = d_rowptr[n], end = d_rowptr[n + 1];
  float accf = 0.f, acce = 0.f;
  for (int p = beg; p < end; p++) {
    int eid = d_eid[p];
    int s = d_esrc[p];
    float no = d_norm_o[s];
    float f = 0.f;
    if (l < 16) f = a_t[s * 16 + l];
    else if (l < 24) f = c_t[s * 8 + (l - 16)];
    else if (l < 27) f = x_t[s * 3 + (l - 24)];
    accf += f * no;
    if (l < 16) acce += e_t[(size_t)eid * 16 + l];
  }
  int deg = end - beg;
  if (l < 27) d_s0[n * 48 + l] = accf * d_norm_i[n];
  if (l < 16) d_s0[n * 48 + 32 + l] = acce / (float)max(deg, 1);
}

// ---------------- layer 0 (writes packed h into d_hn and d_hres) ----------------
__global__ void __launch_bounds__(256) k_layer0(
    const float* __restrict__ W_in, const float* __restrict__ b_in,
    const float* __restrict__ W_e, const float* __restrict__ b_e) {
  __shared__ float st[16][48];
  int j = threadIdx.x;
  int node0 = blockIdx.x * 16;
  float wf[27], we[16];
  #pragma unroll
  for (int k = 0; k < 27; k++) wf[k] = W_in[k * 256 + j];
  #pragma unroll
  for (int k = 0; k < 16; k++) we[k] = W_e[k * 256 + j];
  for (int q = j; q < 16 * 48; q += 256) {
    int r = q / 48, c = q % 48;
    int nd = node0 + r;
    st[r][c] = (nd < NN) ? d_s0[nd * 48 + c] : 0.f;
  }
  __syncthreads();
  float bi = b_in[j], be = b_e[j];
  for (int rr = 0; rr < 16; rr++) {
    int nd = node0 + rr;
    if (nd >= NN) break;
    float v = bi;
    #pragma unroll
    for (int k = 0; k < 27; k++) v += wf[k] * st[rr][k];
    if (d_deg_in[nd] > 0) {
      float e = be;
      #pragma unroll
      for (int k = 0; k < 16; k++) e += we[k] * st[rr][32 + k];
      v += e;
    }
    unsigned pv = pk2(v);
    size_t ix = (size_t)nd * 256 + j;
    d_hn[ix] = pv;
    d_hres[ix] = pv;
  }
}

// ---------------- gather: s = norm_i * sum(norm_o[src] * unpack(hn[src])) -------
__global__ void __launch_bounds__(256) k_gather() {
  __shared__ int ssrc[8][128];
  int wid = threadIdx.x >> 5, l = threadIdx.x & 31;
  int n = blockIdx.x * 8 + wid;
  if (n >= NN) return;
  int beg = d_rowptr[n], end = d_rowptr[n + 1];
  const int gc = l * 8;
  float acc[8];
  #pragma unroll
  for (int c = 0; c < 8; c++) acc[c] = 0.f;
  for (int base = beg; base < end; base += 128) {
    int cnt = min(128, end - base);
    for (int i = l; i < cnt; i += 32) ssrc[wid][i] = d_esrc[base + i];
    __syncwarp();
    int e = 0;
    for (; e + 2 <= cnt; e += 2) {
      int s0 = ssrc[wid][e], s1 = ssrc[wid][e + 1];
      float n0 = d_norm_o[s0], n1 = d_norm_o[s1];
      const uint4* r0 = (const uint4*)(d_hn + (size_t)s0 * 256 + gc);
      const uint4* r1 = (const uint4*)(d_hn + (size_t)s1 * 256 + gc);
      uint4 a0 = r0[0], b0 = r0[1];
      uint4 a1 = r1[0], b1 = r1[1];
      acc[0] += up2(a0.x) * n0 + up2(a1.x) * n1;
      acc[1] += up2(a0.y) * n0 + up2(a1.y) * n1;
      acc[2] += up2(a0.z) * n0 + up2(a1.z) * n1;
      acc[3] += up2(a0.w) * n0 + up2(a1.w) * n1;
      acc[4] += up2(b0.x) * n0 + up2(b1.x) * n1;
      acc[5] += up2(b0.y) * n0 + up2(b1.y) * n1;
      acc[6] += up2(b0.z) * n0 + up2(b1.z) * n1;
      acc[7] += up2(b0.w) * n0 + up2(b1.w) * n1;
    }
    if (e < cnt) {
      int s0 = ssrc[wid][e];
      float n0 = d_norm_o[s0];
      const uint4* r0 = (const uint4*)(d_hn + (size_t)s0 * 256 + gc);
      uint4 a0 = r0[0], b0 = r0[1];
      acc[0] += up2(a0.x) * n0; acc[1] += up2(a0.y) * n0;
      acc[2] += up2(a0.z) * n0; acc[3] += up2(a0.w) * n0;
      acc[4] += up2(b0.x) * n0; acc[5] += up2(b0.y) * n0;
      acc[6] += up2(b0.z) * n0; acc[7] += up2(b0.w) * n0;
    }
    __syncwarp();
  }
  float ni = d_norm_i[n];
  unsigned short hs[8], ls[8];
  #pragma unroll
  for (int c = 0; c < 8; c++) {
    float v = acc[c] * ni;
    hs[c] = __bfloat16_as_ushort(__float2bfloat16(v));
    float hf = __uint_as_float(((unsigned)hs[c]) << 16);
    ls[c] = __bfloat16_as_ushort(__float2bfloat16(v - hf));
  }
  size_t ox = (size_t)n * 256 + gc;
  uint4 hv, lv;
  hv.x = (unsigned)hs[0] | ((unsigned)hs[1] << 16);
  hv.y = (unsigned)hs[2] | ((unsigned)hs[3] << 16);
  hv.z = (unsigned)hs[4] | ((unsigned)hs[5] << 16);
  hv.w = (unsigned)hs[6] | ((unsigned)hs[7] << 16);
  lv.x = (unsigned)ls[0] | ((unsigned)ls[1] << 16);
  lv.y = (unsigned)ls[2] | ((unsigned)ls[3] << 16);
  lv.z = (unsigned)ls[4] | ((unsigned)ls[5] << 16);
  lv.w = (unsigned)ls[6] | ((unsigned)ls[7] << 16);
  *(uint4*)(d_s_hi + ox) = hv;
  *(uint4*)(d_s_lo + ox) = lv;
}

// ---------------- fused GEMM + bias + LN + SiLU + resid + pack ------------------
// block = 64 rows x N=256, 256 threads (8 warps: 2m x 4n), warp tile 32x64.
// smem 100352B -> 2 blocks/SM. BK=16, 2-stage B ring, XOR-16 swizzled B rows.
#define A_ROW 528                          // 512B data + 16 pad
#define A_LIMB (64 * A_ROW)                // 33792
#define B_OFF (2 * A_LIMB)                 // 67584
#define B_LROW 32
#define B_LIMB (256 * B_LROW)              // 8192
#define B_STG (2 * B_LIMB)                 // 16384
#define FUSED_SMEM (B_OFF + 2 * B_STG)     // 100352 bytes

extern __shared__ __align__(16) unsigned char g_sm[];

__global__ void __launch_bounds__(256, 2) k_fused(
    int wslot, const float* __restrict__ bias, const float* __restrict__ gamma,
    const float* __restrict__ beta, int resid) {
  const __nv_bfloat16* wh = d_whi + (size_t)wslot * 65536;
  const __nv_bfloat16* wl = d_wlo + (size_t)wslot * 65536;

  const int t = threadIdx.x;
  const int lane = t & 31;
  const int wid = t >> 5;
  const int wm = wid & 1;       // 0..1 (m)
  const int wn = wid >> 1;      // 0..3 (n)
  const int fr = lane >> 2;
  const int fc = lane & 3;
  const int bm = blockIdx.x * 64;
  const int sel = lane >> 3;
  const int lr = lane & 7;

  unsigned sbase = (unsigned)__cvta_generic_to_shared((void*)g_sm);

  // ---- A dense load: 2 limbs x 64 rows x 32 chunks (16B), zfill OOB rows ----
  #pragma unroll
  for (int i = 0; i < 16; i++) {
    int q = t + 256 * i;
    int limb = q >> 11;
    int r = (q >> 5) & 63;
    int c = q & 31;
    int gr = bm + r;
    bool ok = gr < NN;
    const __nv_bfloat16* srcp = limb ? d_s_lo : d_s_hi;
    cpa16(sbase + limb * A_LIMB + r * A_ROW + c * 16,
          srcp + (size_t)(ok ? gr : 0) * 256 + c * 8, ok);
  }

  // ---- B stage loader (swizzled 32B rows) ----
  auto load_b = [&](int st, int k0) {
    unsigned sb = sbase + B_OFF + st * B_STG;
    #pragma unroll
    for (int i2 = 0; i2 < 2; i2++) {
      int q = t + 256 * i2;             // 512: 256 rows x 2 chunks
      int row = q >> 1, c = q & 1;
      unsigned off = row * B_LROW + ((c ^ ((row >> 2) & 1)) << 4);
      size_t go = (size_t)row * 256 + k0 + c * 8;
      cpa16(sb + off, wh + go, true);
      cpa16(sb + B_LIMB + off, wl + go, true);
    }
    cpa_commit();
  };
  load_b(0, 0);     // commits A + B0 together
  load_b(1, 16);

  // ---- MMA mainloop (16 K16 slabs) ----
  float acc[2][8][4];
  #pragma unroll
  for (int i = 0; i < 2; i++)
    #pragma unroll
    for (int j = 0; j < 8; j++)
      #pragma unroll
      for (int q = 0; q < 4; q++) acc[i][j][q] = 0.f;

  const int a_row = (sel & 1) * 8 + lr;
  const int a_kad = (sel >> 1) * 8;
  const int b_row = (sel >> 1) * 8 + lr;
  const int b_kc  = sel & 1;

  #pragma unroll 1
  for (int s = 0; s < 16; s++) {
    if (s == 15) cpa_wait<0>(); else cpa_wait<1>();
    __syncthreads();
    unsigned sb = sbase + B_OFF + (s & 1) * B_STG;
    const int ka = s * 16;

    unsigned af[2][2][4];
    #pragma unroll
    for (int i = 0; i < 2; i++) {
      int row = wm * 32 + i * 16 + a_row;
      #pragma unroll
      for (int L = 0; L < 2; L++)
        ldsm4(af[i][L], sbase + L * A_LIMB + row * A_ROW + (ka + a_kad) * 2);
    }
    unsigned bf[4][4];
    // B hi
    #pragma unroll
    for (int g = 0; g < 4; g++) {
      int nrow = wn * 64 + g * 16 + b_row;
      ldsm4(bf[g], sb + nrow * B_LROW + ((b_kc ^ ((nrow >> 2) & 1)) << 4));
    }
    #pragma unroll
    for (int i = 0; i < 2; i++)
      #pragma unroll
      for (int g = 0; g < 4; g++) {
        mma_bf16(acc[i][2 * g],     af[i][0], bf[g]);
        mma_bf16(acc[i][2 * g + 1], af[i][0], bf[g] + 2);
        mma_bf16(acc[i][2 * g],     af[i][1], bf[g]);
        mma_bf16(acc[i][2 * g + 1], af[i][1], bf[g] + 2);
      }
    // B lo (x A hi)
    #pragma unroll
    for (int g = 0; g < 4; g++) {
      int nrow = wn * 64 + g * 16 + b_row;
      ldsm4(bf[g], sb + B_LIMB + nrow * B_LROW + ((b_kc ^ ((nrow >> 2) & 1)) << 4));
    }
    #pragma unroll
    for (int i = 0; i < 2; i++)
      #pragma unroll
      for (int g = 0; g < 4; g++) {
        mma_bf16(acc[i][2 * g],     af[i][0], bf[g]);
        mma_bf16(acc[i][2 * g + 1], af[i][0], bf[g] + 2);
      }
    __syncthreads();
    if (s + 2 < 16) load_b(s & 1, (s + 2) * 16);
  }

  // ---- epilogue: bias -> LN -> SiLU -> resid -> pack ----
  __syncthreads();
  float* epi = (float*)g_sm;
  float* psum = epi;              // [64][4]
  float* psq  = epi + 256;        // [64][4]
  float* pmu  = epi + 512;        // [64]
  float* prs  = epi + 576;        // [64]

  #pragma unroll
  for (int j = 0; j < 8; j++) {
    int c0 = wn * 64 + j * 8 + 2 * fc;
    float b0 = bias[c0], b1 = bias[c0 + 1];
    #pragma unroll
    for (int i = 0; i < 2; i++) {
      acc[i][j][0] += b0; acc[i][j][1] += b1;
      acc[i][j][2] += b0; acc[i][j][3] += b1;
    }
  }

  #pragma unroll
  for (int i = 0; i < 2; i++) {
    float s0 = 0.f, q0 = 0.f, s1 = 0.f, q1 = 0.f;
    #pragma unroll
    for (int j = 0; j < 8; j++) {
      s0 += acc[i][j][0] + acc[i][j][1];
      q0 += acc[i][j][0] * acc[i][j][0] + acc[i][j][1] * acc[i][j][1];
      s1 += acc[i][j][2] + acc[i][j][3];
      q1 += acc[i][j][2] * acc[i][j][2] + acc[i][j][3] * acc[i][j][3];
    }
    #pragma unroll
    for (int o = 1; o <= 2; o <<= 1) {
      s0 += __shfl_xor_sync(0xffffffffu, s0, o);
      q0 += __shfl_xor_sync(0xffffffffu, q0, o);
      s1 += __shfl_xor_sync(0xffffffffu, s1, o);
      q1 += __shfl_xor_sync(0xffffffffu, q1, o);
    }
    if (fc == 0) {
      int r0 = wm * 32 + i * 16 + fr;
      psum[r0 * 4 + wn] = s0; psq[r0 * 4 + wn] = q0;
      psum[(r0 + 8) * 4 + wn] = s1; psq[(r0 + 8) * 4 + wn] = q1;
    }
  }
  __syncthreads();
  if (t < 64) {
    float s = psum[t * 4] + psum[t * 4 + 1] + psum[t * 4 + 2] + psum[t * 4 + 3];
    float q = psq[t * 4] + psq[t * 4 + 1] + psq[t * 4 + 2] + psq[t * 4 + 3];
    float mu = s * (1.f / 256.f);
    float var = q * (1.f / 256.f) - mu * mu;
    pmu[t] = mu;
    prs[t] = rsqrtf(var + 1e-5f);
  }
  __syncthreads();

  #pragma unroll
  for (int i = 0; i < 2; i++) {
    int r0l = wm * 32 + i * 16 + fr;
    int r1l = r0l + 8;
    int gr0 = bm + r0l, gr1 = bm + r1l;
    float mu0 = pmu[r0l], rs0 = prs[r0l];
    float mu1 = pmu[r1l], rs1 = prs[r1l];
    #pragma unroll
    for (int j = 0; j < 8; j++) {
      int c0 = wn * 64 + j * 8 + 2 * fc;
      float ga0 = gamma[c0], ga1 = gamma[c0 + 1];
      float be0 = beta[c0], be1 = beta[c0 + 1];
      float y0 = (acc[i][j][0] - mu0) * rs0 * ga0 + be0;
      float y1 = (acc[i][j][1] - mu0) * rs0 * ga1 + be1;
      float y2 = (acc[i][j][2] - mu1) * rs1 * ga0 + be0;
      float y3 = (acc[i][j][3] - mu1) * rs1 * ga1 + be1;
      y0 = y0 / (1.f + __expf(-y0));
      y1 = y1 / (1.f + __expf(-y1));
      y2 = y2 / (1.f + __expf(-y2));
      y3 = y3 / (1.f + __expf(-y3));
      if (gr0 < NN) {
        size_t ix = (size_t)gr0 * 256 + c0;
        uint2 pv;
        if (resid) {
          uint2 old = *(uint2*)(d_hres + ix);
          y0 += up2(old.x); y1 += up2(old.y);
          pv.x = pk2(y0); pv.y = pk2(y1);
          *(uint2*)(d_hres + ix) = pv;
        } else {
          pv.x = pk2(y0); pv.y = pk2(y1);
        }
        *(uint2*)(d_hn + ix) = pv;
      }
      if (gr1 < NN) {
        size_t ix = (size_t)gr1 * 256 + c0;
        uint2 pv;
        if (resid) {
          uint2 old = *(uint2*)(d_hres + ix);
          y2 += up2(old.x); y3 += up2(old.y);
          pv.x = pk2(y2); pv.y = pk2(y3);
          *(uint2*)(d_hres + ix) = pv;
        } else {
          pv.x = pk2(y2); pv.y = pk2(y3);
        }
        *(uint2*)(d_hn + ix) = pv;
      }
    }
  }
}

// ---------------- fused pool + head (graph_id is sorted -> no atomics) ----------
// block g: binary search node range [lo, hi) for graph g, reduce d_hres rows,
// dot with W_head, softplus.
__global__ void __launch_bounds__(256) k_poolhead(
    const int* __restrict__ gid, const float* __restrict__ W_head,
    const float* __restrict__ b_head, float* __restrict__ out) {
  __shared__ float red[8];
  int g = blockIdx.x, j = threadIdx.x;
  // lower_bound(gid, g) and lower_bound(gid, g+1)
  int lo = 0, hi = NN;
  while (lo < hi) { int m = (lo + hi) >> 1; if (gid[m] < g) lo = m + 1; else hi = m; }
  int lo2 = lo, hi2 = NN;
  while (lo2 < hi2) { int m = (lo2 + hi2) >> 1; if (gid[m] < g + 1) lo2 = m + 1; else hi2 = m; }
  float sum = 0.f;
  for (int n = lo; n < lo2; n++)
    sum += up2(d_hres[(size_t)n * 256 + j]);
  float cnt = (float)(lo2 - lo);
  float v = sum / fmaxf(cnt, 1.f) * W_head[j];
  float s = block_sum_256(v, red);
  if (j == 0) {
    float x = s + b_head[0];
    out[g] = (x > 20.f) ? x : log1pf(expf(x));
  }
}

// ---------------- launcher ------------------------------------------------------
extern "C" void kernel_launch(void* const* d_in, const int* in_sizes, int n_in,
                              void* d_out, int out_size) {
  const float* a_t   = (const float*)d_in[0];
  const float* c_t   = (const float*)d_in[1];
  const float* x_t   = (const float*)d_in[2];
  const float* e_t   = (const float*)d_in[3];
  const int*   src   = (const int*)d_in[4];
  const int*   dst   = (const int*)d_in[5];
  const int*   gid   = (const int*)d_in[6];
  const float* W_in  = (const float*)d_in[7];
  const float* b_in  = (const float*)d_in[8];
  const float* W_e   = (const float*)d_in[9];
  const float* b_e   = (const float*)d_in[10];
  const float* Wc1   = (const float*)d_in[11];
  const float* bc1   = (const float*)d_in[12];
  const float* g1    = (const float*)d_in[13];
  const float* be1   = (const float*)d_in[14];
  const float* Wc2   = (const float*)d_in[15];
  const float* bc2   = (const float*)d_in[16];
  const float* g2    = (const float*)d_in[17];
  const float* be2   = (const float*)d_in[18];
  const float* W_hd  = (const float*)d_in[19];
  const float* b_hd  = (const float*)d_in[20];
  float* out = (float*)d_out;

  static bool attr_set = false;
  if (!attr_set) {
    cudaFuncSetAttribute(k_fused, cudaFuncAttributeMaxDynamicSharedMemorySize,
                         FUSED_SMEM);
    attr_set = true;
  }

  const int FGRID = (NN + 63) / 64;   // 782

  k_zero<<<(NN + 255) / 256, 256>>>();
  k_hist<<<(EE + 255) / 256, 256>>>(src, dst);
  k_scan<<<1, 1024>>>();
  k_fill<<<(EE + 255) / 256, 256>>>(src, dst);
  k_norms<<<(NN + 255) / 256, 256>>>();
  k_wsplit<<<(12 * 65536 + 255) / 256, 256>>>(Wc1, Wc2);

  k_gather0<<<(NN + 7) / 8, 256>>>(a_t, c_t, x_t, e_t);
  k_layer0<<<(NN + 15) / 16, 256>>>(W_in, b_in, W_e, b_e);

  for (int l = 0; l < NDEPTH; l++) {
    k_gather<<<(NN + 7) / 8, 256>>>();
    k_fused<<<FGRID, 256, FUSED_SMEM>>>(l, bc1 + l * HH, g1 + l * HH,
                                        be1 + l * HH, 0);
    k_gather<<<(NN + 7) / 8, 256>>>();
    k_fused<<<FGRID, 256, FUSED_SMEM>>>(6 + l, bc2 + l * HH, g2 + l * HH,
                                        be2 + l * HH, 1);
  }

  k_poolhead<<<GG, 256>>>(gid, W_hd, b_hd, out);
}

// round 13
// speedup vs baseline: 1.8743x; 1.4370x over previous
#include <cuda_runtime.h>
#include <cuda_bf16.h>
#include <cuda_fp16.h>
#include <math.h>

#define NN 50000
#define EE 400000
#define GG 256
#define HH 256
#define NDEPTH 6

// ---------------- scratch (device globals) -----------------------------------
__device__ unsigned d_hn[NN * HH];             // packed bf16x2 of h (gather input)
__device__ unsigned d_hres[NN * HH];           // packed bf16x2 residual state
__device__ __half d_s[NN * HH];                // gathered sums, fp16 (GEMM A)
__device__ float d_s0[NN * 48];                // layer-0 gathered feats/edge means
__device__ __half d_wh[12 * HH * HH];          // weights transposed [n][k], fp16
__device__ int   d_deg_in[NN];
__device__ int   d_deg_out[NN];
__device__ int   d_cursor[NN];
__device__ int   d_rowptr[NN + 1];
__device__ int   d_eid[EE];
__device__ int   d_esrc[EE];
__device__ float d_norm_o[NN];
__device__ float d_norm_i[NN];

// ---------------- helpers -----------------------------------------------------
__device__ __forceinline__ float block_sum_256(float v, float* red) {
  #pragma unroll
  for (int o = 16; o > 0; o >>= 1) v += __shfl_down_sync(0xffffffffu, v, o);
  int lane = threadIdx.x & 31, w = threadIdx.x >> 5;
  if (lane == 0) red[w] = v;
  __syncthreads();
  if (threadIdx.x < 8) {
    float x = red[threadIdx.x];
    #pragma unroll
    for (int o = 4; o > 0; o >>= 1) x += __shfl_down_sync(0xffu, x, o);
    if (threadIdx.x == 0) red[0] = x;
  }
  __syncthreads();
  float r = red[0];
  __syncthreads();
  return r;
}

__device__ __forceinline__ float up2(unsigned u) {
  return __uint_as_float(u << 16) + __uint_as_float(u & 0xffff0000u);
}
__device__ __forceinline__ unsigned pk2(float x) {
  unsigned short h = __bfloat16_as_ushort(__float2bfloat16(x));
  float hf = __uint_as_float(((unsigned)h) << 16);
  unsigned short l = __bfloat16_as_ushort(__float2bfloat16(x - hf));
  return (unsigned)h | (((unsigned)l) << 16);
}
__device__ __forceinline__ unsigned h2pack(float a, float b) {
  return (unsigned)__half_as_ushort(__float2half_rn(a)) |
         ((unsigned)__half_as_ushort(__float2half_rn(b)) << 16);
}

__device__ __forceinline__ void mma_f16(float* c, const unsigned* a, const unsigned* b) {
  asm volatile(
      "mma.sync.aligned.m16n8k16.row.col.f32.f16.f16.f32 "
      "{%0,%1,%2,%3}, {%4,%5,%6,%7}, {%8,%9}, {%0,%1,%2,%3};\n"
      : "+f"(c[0]), "+f"(c[1]), "+f"(c[2]), "+f"(c[3])
      : "r"(a[0]), "r"(a[1]), "r"(a[2]), "r"(a[3]), "r"(b[0]), "r"(b[1]));
}

__device__ __forceinline__ void ldsm4(unsigned* r, unsigned saddr) {
  asm volatile("ldmatrix.sync.aligned.m8n8.x4.shared.b16 {%0,%1,%2,%3}, [%4];"
               : "=r"(r[0]), "=r"(r[1]), "=r"(r[2]), "=r"(r[3]) : "r"(saddr));
}

__device__ __forceinline__ void cpa16(unsigned saddr, const void* gaddr, bool pred) {
  int sz = pred ? 16 : 0;
  asm volatile("cp.async.cg.shared.global [%0], [%1], 16, %2;\n"
               :: "r"(saddr), "l"(gaddr), "r"(sz));
}
__device__ __forceinline__ void cpa_commit() {
  asm volatile("cp.async.commit_group;\n");
}
template <int N>
__device__ __forceinline__ void cpa_wait() {
  asm volatile("cp.async.wait_group %0;\n" :: "n"(N));
}

// ---------------- preprocessing -----------------------------------------------
__global__ void k_zero() {
  int i = blockIdx.x * blockDim.x + threadIdx.x;
  if (i < NN) { d_deg_in[i] = 0; d_deg_out[i] = 0; d_cursor[i] = 0; }
}

__global__ void k_hist(const int* __restrict__ src, const int* __restrict__ dst) {
  int e = blockIdx.x * blockDim.x + threadIdx.x;
  if (e < EE) {
    atomicAdd(&d_deg_in[dst[e]], 1);
    atomicAdd(&d_deg_out[src[e]], 1);
  }
}

__global__ void k_scan() {
  __shared__ int warp_tot[32];
  __shared__ int s_carry;
  int t = threadIdx.x, lane = t & 31, w = t >> 5;
  if (t == 0) s_carry = 0;
  __syncthreads();
  for (int base = 0; base < NN; base += 1024) {
    int v = (base + t < NN) ? d_deg_in[base + t] : 0;
    int x = v;
    #pragma unroll
    for (int o = 1; o < 32; o <<= 1) {
      int y = __shfl_up_sync(0xffffffffu, x, o);
      if (lane >= o) x += y;
    }
    if (lane == 31) warp_tot[w] = x;
    __syncthreads();
    if (w == 0) {
      int y = warp_tot[lane];
      int z = y;
      #pragma unroll
      for (int o = 1; o < 32; o <<= 1) {
        int q = __shfl_up_sync(0xffffffffu, z, o);
        if (lane >= o) z += q;
      }
      warp_tot[lane] = z - y;
    }
    __syncthreads();
    int incl = x + warp_tot[w];
    int carry = s_carry;
    if (base + t < NN) d_rowptr[base + t] = carry + incl - v;
    __syncthreads();
    if (t == 1023) s_carry = carry + incl;
    __syncthreads();
  }
  if (threadIdx.x == 0) d_rowptr[NN] = s_carry;
}

__global__ void k_fill(const int* __restrict__ src, const int* __restrict__ dst) {
  int e = blockIdx.x * blockDim.x + threadIdx.x;
  if (e < EE) {
    int dnode = dst[e];
    int pos = atomicAdd(&d_cursor[dnode], 1);
    int idx = d_rowptr[dnode] + pos;
    d_eid[idx] = e;
    d_esrc[idx] = src[e];
  }
}

__global__ void k_norms() {
  int i = blockIdx.x * blockDim.x + threadIdx.x;
  if (i < NN) {
    int di = d_deg_in[i];
    int dq = d_deg_out[i];
    d_norm_i[i] = (di > 0) ? rsqrtf((float)di) : 0.f;
    d_norm_o[i] = (dq > 0) ? rsqrtf((float)dq) : 0.f;
  }
}

// convert + transpose all 12 weight matrices into fp16 [n][k]
__global__ void k_wcvt(const float* __restrict__ Wc1, const float* __restrict__ Wc2) {
  int i = blockIdx.x * blockDim.x + threadIdx.x;
  if (i >= 12 * 65536) return;
  int slot = i >> 16, r = i & 65535;
  int k = r >> 8, n = r & 255;
  float w = (slot < 6) ? Wc1[(size_t)slot * 65536 + k * 256 + n]
                       : Wc2[(size_t)(slot - 6) * 65536 + k * 256 + n];
  d_wh[(size_t)slot * 65536 + n * 256 + k] = __float2half_rn(w);
}

// ---------------- layer-0 gather ------------------------------------------------
__global__ void __launch_bounds__(256) k_gather0(
    const float* __restrict__ a_t, const float* __restrict__ c_t,
    const float* __restrict__ x_t, const float* __restrict__ e_t) {
  int wid = threadIdx.x >> 5, l = threadIdx.x & 31;
  int n = blockIdx.x * 8 + wid;
  if (n >= NN) return;
  int beg = d_rowptr[n], end = d_rowptr[n + 1];
  float accf = 0.f, acce = 0.f;
  for (int p = beg; p < end; p++) {
    int eid = d_eid[p];
    int s = d_esrc[p];
    float no = d_norm_o[s];
    float f = 0.f;
    if (l < 16) f = a_t[s * 16 + l];
    else if (l < 24) f = c_t[s * 8 + (l - 16)];
    else if (l < 27) f = x_t[s * 3 + (l - 24)];
    accf += f * no;
    if (l < 16) acce += e_t[(size_t)eid * 16 + l];
  }
  int deg = end - beg;
  if (l < 27) d_s0[n * 48 + l] = accf * d_norm_i[n];
  if (l < 16) d_s0[n * 48 + 32 + l] = acce / (float)max(deg, 1);
}

// ---------------- layer 0 (writes packed h into d_hn and d_hres) ----------------
__global__ void __launch_bounds__(256) k_layer0(
    const float* __restrict__ W_in, const float* __restrict__ b_in,
    const float* __restrict__ W_e, const float* __restrict__ b_e) {
  __shared__ float st[16][48];
  int j = threadIdx.x;
  int node0 = blockIdx.x * 16;
  float wf[27], we[16];
  #pragma unroll
  for (int k = 0; k < 27; k++) wf[k] = W_in[k * 256 + j];
  #pragma unroll
  for (int k = 0; k < 16; k++) we[k] = W_e[k * 256 + j];
  for (int q = j; q < 16 * 48; q += 256) {
    int r = q / 48, c = q % 48;
    int nd = node0 + r;
    st[r][c] = (nd < NN) ? d_s0[nd * 48 + c] : 0.f;
  }
  __syncthreads();
  float bi = b_in[j], be = b_e[j];
  for (int rr = 0; rr < 16; rr++) {
    int nd = node0 + rr;
    if (nd >= NN) break;
    float v = bi;
    #pragma unroll
    for (int k = 0; k < 27; k++) v += wf[k] * st[rr][k];
    if (d_deg_in[nd] > 0) {
      float e = be;
      #pragma unroll
      for (int k = 0; k < 16; k++) e += we[k] * st[rr][32 + k];
      v += e;
    }
    unsigned pv = pk2(v);
    size_t ix = (size_t)nd * 256 + j;
    d_hn[ix] = pv;
    d_hres[ix] = pv;
  }
}

// ---------------- gather: s = norm_i * sum(norm_o[src] * unpack(hn[src])) -------
// warp per dst node; lane covers 8 contiguous cols. Output: fp16 (GEMM A).
__global__ void __launch_bounds__(256) k_gather() {
  __shared__ int ssrc[8][128];
  int wid = threadIdx.x >> 5, l = threadIdx.x & 31;
  int n = blockIdx.x * 8 + wid;
  if (n >= NN) return;
  int beg = d_rowptr[n], end = d_rowptr[n + 1];
  const int gc = l * 8;
  float acc[8];
  #pragma unroll
  for (int c = 0; c < 8; c++) acc[c] = 0.f;
  for (int base = beg; base < end; base += 128) {
    int cnt = min(128, end - base);
    for (int i = l; i < cnt; i += 32) ssrc[wid][i] = d_esrc[base + i];
    __syncwarp();
    int e = 0;
    for (; e + 2 <= cnt; e += 2) {
      int s0 = ssrc[wid][e], s1 = ssrc[wid][e + 1];
      float n0 = d_norm_o[s0], n1 = d_norm_o[s1];
      const uint4* r0 = (const uint4*)(d_hn + (size_t)s0 * 256 + gc);
      const uint4* r1 = (const uint4*)(d_hn + (size_t)s1 * 256 + gc);
      uint4 a0 = r0[0], b0 = r0[1];
      uint4 a1 = r1[0], b1 = r1[1];
      acc[0] += up2(a0.x) * n0 + up2(a1.x) * n1;
      acc[1] += up2(a0.y) * n0 + up2(a1.y) * n1;
      acc[2] += up2(a0.z) * n0 + up2(a1.z) * n1;
      acc[3] += up2(a0.w) * n0 + up2(a1.w) * n1;
      acc[4] += up2(b0.x) * n0 + up2(b1.x) * n1;
      acc[5] += up2(b0.y) * n0 + up2(b1.y) * n1;
      acc[6] += up2(b0.z) * n0 + up2(b1.z) * n1;
      acc[7] += up2(b0.w) * n0 + up2(b1.w) * n1;
    }
    if (e < cnt) {
      int s0 = ssrc[wid][e];
      float n0 = d_norm_o[s0];
      const uint4* r0 = (const uint4*)(d_hn + (size_t)s0 * 256 + gc);
      uint4 a0 = r0[0], b0 = r0[1];
      acc[0] += up2(a0.x) * n0; acc[1] += up2(a0.y) * n0;
      acc[2] += up2(a0.z) * n0; acc[3] += up2(a0.w) * n0;
      acc[4] += up2(b0.x) * n0; acc[5] += up2(b0.y) * n0;
      acc[6] += up2(b0.z) * n0; acc[7] += up2(b0.w) * n0;
    }
    __syncwarp();
  }
  float ni = d_norm_i[n];
  uint4 hv;
  hv.x = h2pack(acc[0] * ni, acc[1] * ni);
  hv.y = h2pack(acc[2] * ni, acc[3] * ni);
  hv.z = h2pack(acc[4] * ni, acc[5] * ni);
  hv.w = h2pack(acc[6] * ni, acc[7] * ni);
  *(uint4*)(d_s + (size_t)n * 256 + gc) = hv;
}

// ---------------- fused GEMM + bias + LN + SiLU + resid + pack ------------------
// block = 64 rows x N=256, 256 threads (8 warps: 2m x 4n), warp tile 32x64.
// fp16 x fp16 -> f32 MMA (single product). smem 50176B -> 2 blocks/SM.
#define A_ROW 528                          // 512B data + 16 pad
#define A_SZ (64 * A_ROW)                  // 33792
#define B_OFF A_SZ
#define B_LROW 32
#define B_STG (256 * B_LROW)               // 8192 per stage
#define FUSED_SMEM (B_OFF + 2 * B_STG)     // 50176 bytes

extern __shared__ __align__(16) unsigned char g_sm[];

__global__ void __launch_bounds__(256, 2) k_fused(
    int wslot, const float* __restrict__ bias, const float* __restrict__ gamma,
    const float* __restrict__ beta, int resid) {
  const __half* wh = d_wh + (size_t)wslot * 65536;

  const int t = threadIdx.x;
  const int lane = t & 31;
  const int wid = t >> 5;
  const int wm = wid & 1;       // 0..1 (m)
  const int wn = wid >> 1;      // 0..3 (n)
  const int fr = lane >> 2;
  const int fc = lane & 3;
  const int bm = blockIdx.x * 64;
  const int sel = lane >> 3;
  const int lr = lane & 7;

  unsigned sbase = (unsigned)__cvta_generic_to_shared((void*)g_sm);

  // ---- A dense load: 64 rows x 32 chunks (16B), zfill OOB rows ----
  #pragma unroll
  for (int i = 0; i < 8; i++) {
    int q = t + 256 * i;
    int r = q >> 5;
    int c = q & 31;
    int gr = bm + r;
    bool ok = gr < NN;
    cpa16(sbase + r * A_ROW + c * 16,
          d_s + (size_t)(ok ? gr : 0) * 256 + c * 8, ok);
  }

  // ---- B stage loader (swizzled 32B rows, single fp16 limb) ----
  auto load_b = [&](int st, int k0) {
    unsigned sb = sbase + B_OFF + st * B_STG;
    #pragma unroll
    for (int i2 = 0; i2 < 2; i2++) {
      int q = t + 256 * i2;             // 512: 256 rows x 2 chunks
      int row = q >> 1, c = q & 1;
      unsigned off = row * B_LROW + ((c ^ ((row >> 2) & 1)) << 4);
      cpa16(sb + off, wh + (size_t)row * 256 + k0 + c * 8, true);
    }
    cpa_commit();
  };
  load_b(0, 0);     // commits A + B0 together
  load_b(1, 16);

  // ---- MMA mainloop (16 K16 slabs) ----
  float acc[2][8][4];
  #pragma unroll
  for (int i = 0; i < 2; i++)
    #pragma unroll
    for (int j = 0; j < 8; j++)
      #pragma unroll
      for (int q = 0; q < 4; q++) acc[i][j][q] = 0.f;

  const int a_row = (sel & 1) * 8 + lr;
  const int a_kad = (sel >> 1) * 8;
  const int b_row = (sel >> 1) * 8 + lr;
  const int b_kc  = sel & 1;

  #pragma unroll 1
  for (int s = 0; s < 16; s++) {
    if (s == 15) cpa_wait<0>(); else cpa_wait<1>();
    __syncthreads();
    unsigned sb = sbase + B_OFF + (s & 1) * B_STG;
    const int ka = s * 16;

    unsigned af[2][4];
    #pragma unroll
    for (int i = 0; i < 2; i++) {
      int row = wm * 32 + i * 16 + a_row;
      ldsm4(af[i], sbase + row * A_ROW + (ka + a_kad) * 2);
    }
    unsigned bf[4][4];
    #pragma unroll
    for (int g = 0; g < 4; g++) {
      int nrow = wn * 64 + g * 16 + b_row;
      ldsm4(bf[g], sb + nrow * B_LROW + ((b_kc ^ ((nrow >> 2) & 1)) << 4));
    }
    #pragma unroll
    for (int i = 0; i < 2; i++)
      #pragma unroll
      for (int g = 0; g < 4; g++) {
        mma_f16(acc[i][2 * g],     af[i], bf[g]);
        mma_f16(acc[i][2 * g + 1], af[i], bf[g] + 2);
      }
    __syncthreads();
    if (s + 2 < 16) load_b(s & 1, (s + 2) * 16);
  }

  // ---- epilogue: bias -> LN -> SiLU -> resid -> pack ----
  __syncthreads();
  float* epi = (float*)g_sm;
  float* psum = epi;              // [64][4]
  float* psq  = epi + 256;        // [64][4]
  float* pmu  = epi + 512;        // [64]
  float* prs  = epi + 576;        // [64]

  #pragma unroll
  for (int j = 0; j < 8; j++) {
    int c0 = wn * 64 + j * 8 + 2 * fc;
    float b0 = bias[c0], b1 = bias[c0 + 1];
    #pragma unroll
    for (int i = 0; i < 2; i++) {
      acc[i][j][0] += b0; acc[i][j][1] += b1;
      acc[i][j][2] += b0; acc[i][j][3] += b1;
    }
  }

  #pragma unroll
  for (int i = 0; i < 2; i++) {
    float s0 = 0.f, q0 = 0.f, s1 = 0.f, q1 = 0.f;
    #pragma unroll
    for (int j = 0; j < 8; j++) {
      s0 += acc[i][j][0] + acc[i][j][1];
      q0 += acc[i][j][0] * acc[i][j][0] + acc[i][j][1] * acc[i][j][1];
      s1 += acc[i][j][2] + acc[i][j][3];
      q1 += acc[i][j][2] * acc[i][j][2] + acc[i][j][3] * acc[i][j][3];
    }
    #pragma unroll
    for (int o = 1; o <= 2; o <<= 1) {
      s0 += __shfl_xor_sync(0xffffffffu, s0, o);
      q0 += __shfl_xor_sync(0xffffffffu, q0, o);
      s1 += __shfl_xor_sync(0xffffffffu, s1, o);
      q1 += __shfl_xor_sync(0xffffffffu, q1, o);
    }
    if (fc == 0) {
      int r0 = wm * 32 + i * 16 + fr;
      psum[r0 * 4 + wn] = s0; psq[r0 * 4 + wn] = q0;
      psum[(r0 + 8) * 4 + wn] = s1; psq[(r0 + 8) * 4 + wn] = q1;
    }
  }
  __syncthreads();
  if (t < 64) {
    float s = psum[t * 4] + psum[t * 4 + 1] + psum[t * 4 + 2] + psum[t * 4 + 3];
    float q = psq[t * 4] + psq[t * 4 + 1] + psq[t * 4 + 2] + psq[t * 4 + 3];
    float mu = s * (1.f / 256.f);
    float var = q * (1.f / 256.f) - mu * mu;
    pmu[t] = mu;
    prs[t] = rsqrtf(var + 1e-5f);
  }
  __syncthreads();

  #pragma unroll
  for (int i = 0; i < 2; i++) {
    int r0l = wm * 32 + i * 16 + fr;
    int r1l = r0l + 8;
    int gr0 = bm + r0l, gr1 = bm + r1l;
    float mu0 = pmu[r0l], rs0 = prs[r0l];
    float mu1 = pmu[r1l], rs1 = prs[r1l];
    #pragma unroll
    for (int j = 0; j < 8; j++) {
      int c0 = wn * 64 + j * 8 + 2 * fc;
      float ga0 = gamma[c0], ga1 = gamma[c0 + 1];
      float be0 = beta[c0], be1 = beta[c0 + 1];
      float y0 = (acc[i][j][0] - mu0) * rs0 * ga0 + be0;
      float y1 = (acc[i][j][1] - mu0) * rs0 * ga1 + be1;
      float y2 = (acc[i][j][2] - mu1) * rs1 * ga0 + be0;
      float y3 = (acc[i][j][3] - mu1) * rs1 * ga1 + be1;
      y0 = __fdividef(y0, 1.f + __expf(-y0));
      y1 = __fdividef(y1, 1.f + __expf(-y1));
      y2 = __fdividef(y2, 1.f + __expf(-y2));
      y3 = __fdividef(y3, 1.f + __expf(-y3));
      if (gr0 < NN) {
        size_t ix = (size_t)gr0 * 256 + c0;
        uint2 pv;
        if (resid) {
          uint2 old = *(uint2*)(d_hres + ix);
          y0 += up2(old.x); y1 += up2(old.y);
          pv.x = pk2(y0); pv.y = pk2(y1);
          *(uint2*)(d_hres + ix) = pv;
        } else {
          pv.x = pk2(y0); pv.y = pk2(y1);
        }
        *(uint2*)(d_hn + ix) = pv;
      }
      if (gr1 < NN) {
        size_t ix = (size_t)gr1 * 256 + c0;
        uint2 pv;
        if (resid) {
          uint2 old = *(uint2*)(d_hres + ix);
          y2 += up2(old.x); y3 += up2(old.y);
          pv.x = pk2(y2); pv.y = pk2(y3);
          *(uint2*)(d_hres + ix) = pv;
        } else {
          pv.x = pk2(y2); pv.y = pk2(y3);
        }
        *(uint2*)(d_hn + ix) = pv;
      }
    }
  }
}

// ---------------- fused pool + head (graph_id sorted -> no atomics) -------------
__global__ void __launch_bounds__(256) k_poolhead(
    const int* __restrict__ gid, const float* __restrict__ W_head,
    const float* __restrict__ b_head, float* __restrict__ out) {
  __shared__ float red[8];
  int g = blockIdx.x, j = threadIdx.x;
  int lo = 0, hi = NN;
  while (lo < hi) { int m = (lo + hi) >> 1; if (gid[m] < g) lo = m + 1; else hi = m; }
  int lo2 = lo, hi2 = NN;
  while (lo2 < hi2) { int m = (lo2 + hi2) >> 1; if (gid[m] < g + 1) lo2 = m + 1; else hi2 = m; }
  float sum = 0.f;
  for (int n = lo; n < lo2; n++)
    sum += up2(d_hres[(size_t)n * 256 + j]);
  float cnt = (float)(lo2 - lo);
  float v = sum / fmaxf(cnt, 1.f) * W_head[j];
  float s = block_sum_256(v, red);
  if (j == 0) {
    float x = s + b_head[0];
    out[g] = (x > 20.f) ? x : log1pf(expf(x));
  }
}

// ---------------- launcher ------------------------------------------------------
extern "C" void kernel_launch(void* const* d_in, const int* in_sizes, int n_in,
                              void* d_out, int out_size) {
  const float* a_t   = (const float*)d_in[0];
  const float* c_t   = (const float*)d_in[1];
  const float* x_t   = (const float*)d_in[2];
  const float* e_t   = (const float*)d_in[3];
  const int*   src   = (const int*)d_in[4];
  const int*   dst   = (const int*)d_in[5];
  const int*   gid   = (const int*)d_in[6];
  const float* W_in  = (const float*)d_in[7];
  const float* b_in  = (const float*)d_in[8];
  const float* W_e   = (const float*)d_in[9];
  const float* b_e   = (const float*)d_in[10];
  const float* Wc1   = (const float*)d_in[11];
  const float* bc1   = (const float*)d_in[12];
  const float* g1    = (const float*)d_in[13];
  const float* be1   = (const float*)d_in[14];
  const float* Wc2   = (const float*)d_in[15];
  const float* bc2   = (const float*)d_in[16];
  const float* g2    = (const float*)d_in[17];
  const float* be2   = (const float*)d_in[18];
  const float* W_hd  = (const float*)d_in[19];
  const float* b_hd  = (const float*)d_in[20];
  float* out = (float*)d_out;

  static bool attr_set = false;
  if (!attr_set) {
    cudaFuncSetAttribute(k_fused, cudaFuncAttributeMaxDynamicSharedMemorySize,
                         FUSED_SMEM);
    attr_set = true;
  }

  const int FGRID = (NN + 63) / 64;   // 782

  k_zero<<<(NN + 255) / 256, 256>>>();
  k_hist<<<(EE + 255) / 256, 256>>>(src, dst);
  k_scan<<<1, 1024>>>();
  k_fill<<<(EE + 255) / 256, 256>>>(src, dst);
  k_norms<<<(NN + 255) / 256, 256>>>();
  k_wcvt<<<(12 * 65536 + 255) / 256, 256>>>(Wc1, Wc2);

  k_gather0<<<(NN + 7) / 8, 256>>>(a_t, c_t, x_t, e_t);
  k_layer0<<<(NN + 15) / 16, 256>>>(W_in, b_in, W_e, b_e);

  for (int l = 0; l < NDEPTH; l++) {
    k_gather<<<(NN + 7) / 8, 256>>>();
    k_fused<<<FGRID, 256, FUSED_SMEM>>>(l, bc1 + l * HH, g1 + l * HH,
                                        be1 + l * HH, 0);
    k_gather<<<(NN + 7) / 8, 256>>>();
    k_fused<<<FGRID, 256, FUSED_SMEM>>>(6 + l, bc2 + l * HH, g2 + l * HH,
                                        be2 + l * HH, 1);
  }

  k_poolhead<<<GG, 256>>>(gid, W_hd, b_hd, out);
}

// round 14
// speedup vs baseline: 2.1927x; 1.1699x over previous
#include <cuda_runtime.h>
#include <cuda_bf16.h>
#include <cuda_fp16.h>
#include <math.h>

#define NN 50000
#define EE 400000
#define GG 256
#define HH 256
#define NDEPTH 6
#define HSTRIDE 512   // fp16 elements per d_hn row (512B data + 512B pad = 1024B)

// ---------------- scratch (device globals) -----------------------------------
__device__ __half d_hn[(size_t)NN * HSTRIDE];  // fp16 h, 1024B row stride
__device__ unsigned d_hres[NN * HH];           // packed bf16x2 residual state
__device__ __half d_s[NN * HH];                // gathered sums, fp16 (GEMM A)
__device__ float d_s0[NN * 48];                // layer-0 gathered feats/edge means
__device__ __half d_wh[12 * HH * HH];          // weights transposed [n][k], fp16
__device__ int   d_deg_in[NN];
__device__ int   d_deg_out[NN];
__device__ int   d_cursor[NN];
__device__ int   d_rowptr[NN + 1];
__device__ int   d_eid[EE];
__device__ int   d_esrc[EE];
__device__ float d_norm_o[NN];
__device__ float d_norm_i[NN];

// ---------------- helpers -----------------------------------------------------
__device__ __forceinline__ float block_sum_256(float v, float* red) {
  #pragma unroll
  for (int o = 16; o > 0; o >>= 1) v += __shfl_down_sync(0xffffffffu, v, o);
  int lane = threadIdx.x & 31, w = threadIdx.x >> 5;
  if (lane == 0) red[w] = v;
  __syncthreads();
  if (threadIdx.x < 8) {
    float x = red[threadIdx.x];
    #pragma unroll
    for (int o = 4; o > 0; o >>= 1) x += __shfl_down_sync(0xffu, x, o);
    if (threadIdx.x == 0) red[0] = x;
  }
  __syncthreads();
  float r = red[0];
  __syncthreads();
  return r;
}

__device__ __forceinline__ float up2(unsigned u) {
  return __uint_as_float(u << 16) + __uint_as_float(u & 0xffff0000u);
}
__device__ __forceinline__ unsigned pk2(float x) {
  unsigned short h = __bfloat16_as_ushort(__float2bfloat16(x));
  float hf = __uint_as_float(((unsigned)h) << 16);
  unsigned short l = __bfloat16_as_ushort(__float2bfloat16(x - hf));
  return (unsigned)h | (((unsigned)l) << 16);
}
__device__ __forceinline__ unsigned h2pack(float a, float b) {
  return (unsigned)__half_as_ushort(__float2half_rn(a)) |
         ((unsigned)__half_as_ushort(__float2half_rn(b)) << 16);
}

__device__ __forceinline__ void mma_f16(float* c, const unsigned* a, const unsigned* b) {
  asm volatile(
      "mma.sync.aligned.m16n8k16.row.col.f32.f16.f16.f32 "
      "{%0,%1,%2,%3}, {%4,%5,%6,%7}, {%8,%9}, {%0,%1,%2,%3};\n"
      : "+f"(c[0]), "+f"(c[1]), "+f"(c[2]), "+f"(c[3])
      : "r"(a[0]), "r"(a[1]), "r"(a[2]), "r"(a[3]), "r"(b[0]), "r"(b[1]));
}

__device__ __forceinline__ void ldsm4(unsigned* r, unsigned saddr) {
  asm volatile("ldmatrix.sync.aligned.m8n8.x4.shared.b16 {%0,%1,%2,%3}, [%4];"
               : "=r"(r[0]), "=r"(r[1]), "=r"(r[2]), "=r"(r[3]) : "r"(saddr));
}

__device__ __forceinline__ void cpa16(unsigned saddr, const void* gaddr, bool pred) {
  int sz = pred ? 16 : 0;
  asm volatile("cp.async.cg.shared.global [%0], [%1], 16, %2;\n"
               :: "r"(saddr), "l"(gaddr), "r"(sz));
}
__device__ __forceinline__ void cpa_commit() {
  asm volatile("cp.async.commit_group;\n");
}
template <int N>
__device__ __forceinline__ void cpa_wait() {
  asm volatile("cp.async.wait_group %0;\n" :: "n"(N));
}

// ---------------- preprocessing -----------------------------------------------
__global__ void k_zero() {
  int i = blockIdx.x * blockDim.x + threadIdx.x;
  if (i < NN) { d_deg_in[i] = 0; d_deg_out[i] = 0; d_cursor[i] = 0; }
}

__global__ void k_hist(const int* __restrict__ src, const int* __restrict__ dst) {
  int e = blockIdx.x * blockDim.x + threadIdx.x;
  if (e < EE) {
    atomicAdd(&d_deg_in[dst[e]], 1);
    atomicAdd(&d_deg_out[src[e]], 1);
  }
}

__global__ void k_scan() {
  __shared__ int warp_tot[32];
  __shared__ int s_carry;
  int t = threadIdx.x, lane = t & 31, w = t >> 5;
  if (t == 0) s_carry = 0;
  __syncthreads();
  for (int base = 0; base < NN; base += 1024) {
    int v = (base + t < NN) ? d_deg_in[base + t] : 0;
    int x = v;
    #pragma unroll
    for (int o = 1; o < 32; o <<= 1) {
      int y = __shfl_up_sync(0xffffffffu, x, o);
      if (lane >= o) x += y;
    }
    if (lane == 31) warp_tot[w] = x;
    __syncthreads();
    if (w == 0) {
      int y = warp_tot[lane];
      int z = y;
      #pragma unroll
      for (int o = 1; o < 32; o <<= 1) {
        int q = __shfl_up_sync(0xffffffffu, z, o);
        if (lane >= o) z += q;
      }
      warp_tot[lane] = z - y;
    }
    __syncthreads();
    int incl = x + warp_tot[w];
    int carry = s_carry;
    if (base + t < NN) d_rowptr[base + t] = carry + incl - v;
    __syncthreads();
    if (t == 1023) s_carry = carry + incl;
    __syncthreads();
  }
  if (threadIdx.x == 0) d_rowptr[NN] = s_carry;
}

__global__ void k_fill(const int* __restrict__ src, const int* __restrict__ dst) {
  int e = blockIdx.x * blockDim.x + threadIdx.x;
  if (e < EE) {
    int dnode = dst[e];
    int pos = atomicAdd(&d_cursor[dnode], 1);
    int idx = d_rowptr[dnode] + pos;
    d_eid[idx] = e;
    d_esrc[idx] = src[e];
  }
}

__global__ void k_norms() {
  int i = blockIdx.x * blockDim.x + threadIdx.x;
  if (i < NN) {
    int di = d_deg_in[i];
    int dq = d_deg_out[i];
    d_norm_i[i] = (di > 0) ? rsqrtf((float)di) : 0.f;
    d_norm_o[i] = (dq > 0) ? rsqrtf((float)dq) : 0.f;
  }
}

// convert + transpose all 12 weight matrices into fp16 [n][k]
__global__ void k_wcvt(const float* __restrict__ Wc1, const float* __restrict__ Wc2) {
  int i = blockIdx.x * blockDim.x + threadIdx.x;
  if (i >= 12 * 65536) return;
  int slot = i >> 16, r = i & 65535;
  int k = r >> 8, n = r & 255;
  float w = (slot < 6) ? Wc1[(size_t)slot * 65536 + k * 256 + n]
                       : Wc2[(size_t)(slot - 6) * 65536 + k * 256 + n];
  d_wh[(size_t)slot * 65536 + n * 256 + k] = __float2half_rn(w);
}

// ---------------- layer-0 gather ------------------------------------------------
__global__ void __launch_bounds__(256) k_gather0(
    const float* __restrict__ a_t, const float* __restrict__ c_t,
    const float* __restrict__ x_t, const float* __restrict__ e_t) {
  int wid = threadIdx.x >> 5, l = threadIdx.x & 31;
  int n = blockIdx.x * 8 + wid;
  if (n >= NN) return;
  int beg = d_rowptr[n], end = d_rowptr[n + 1];
  float accf = 0.f, acce = 0.f;
  for (int p = beg; p < end; p++) {
    int eid = d_eid[p];
    int s = d_esrc[p];
    float no = d_norm_o[s];
    float f = 0.f;
    if (l < 16) f = a_t[s * 16 + l];
    else if (l < 24) f = c_t[s * 8 + (l - 16)];
    else if (l < 27) f = x_t[s * 3 + (l - 24)];
    accf += f * no;
    if (l < 16) acce += e_t[(size_t)eid * 16 + l];
  }
  int deg = end - beg;
  if (l < 27) d_s0[n * 48 + l] = accf * d_norm_i[n];
  if (l < 16) d_s0[n * 48 + 32 + l] = acce / (float)max(deg, 1);
}

// ---------------- layer 0 (writes fp16 h into d_hn, bf16x2 into d_hres) ---------
__global__ void __launch_bounds__(256) k_layer0(
    const float* __restrict__ W_in, const float* __restrict__ b_in,
    const float* __restrict__ W_e, const float* __restrict__ b_e) {
  __shared__ float st[16][48];
  int j = threadIdx.x;
  int node0 = blockIdx.x * 16;
  float wf[27], we[16];
  #pragma unroll
  for (int k = 0; k < 27; k++) wf[k] = W_in[k * 256 + j];
  #pragma unroll
  for (int k = 0; k < 16; k++) we[k] = W_e[k * 256 + j];
  for (int q = j; q < 16 * 48; q += 256) {
    int r = q / 48, c = q % 48;
    int nd = node0 + r;
    st[r][c] = (nd < NN) ? d_s0[nd * 48 + c] : 0.f;
  }
  __syncthreads();
  float bi = b_in[j], be = b_e[j];
  for (int rr = 0; rr < 16; rr++) {
    int nd = node0 + rr;
    if (nd >= NN) break;
    float v = bi;
    #pragma unroll
    for (int k = 0; k < 27; k++) v += wf[k] * st[rr][k];
    if (d_deg_in[nd] > 0) {
      float e = be;
      #pragma unroll
      for (int k = 0; k < 16; k++) e += we[k] * st[rr][32 + k];
      v += e;
    }
    d_hn[(size_t)nd * HSTRIDE + j] = __float2half_rn(v);
    d_hres[(size_t)nd * 256 + j] = pk2(v);
  }
}

// ---------------- gather: s = norm_i * sum(norm_o[src] * fp16 hn[src]) ----------
// warp per dst node; lane covers 8 contiguous cols (one uint4 / 16B per row).
__global__ void __launch_bounds__(256) k_gather() {
  __shared__ int ssrc[8][128];
  int wid = threadIdx.x >> 5, l = threadIdx.x & 31;
  int n = blockIdx.x * 8 + wid;
  if (n >= NN) return;
  int beg = d_rowptr[n], end = d_rowptr[n + 1];
  const int gc = l * 8;
  float acc[8];
  #pragma unroll
  for (int c = 0; c < 8; c++) acc[c] = 0.f;
  for (int base = beg; base < end; base += 128) {
    int cnt = min(128, end - base);
    for (int i = l; i < cnt; i += 32) ssrc[wid][i] = d_esrc[base + i];
    __syncwarp();
    int e = 0;
    for (; e + 2 <= cnt; e += 2) {
      int s0 = ssrc[wid][e], s1 = ssrc[wid][e + 1];
      float n0 = d_norm_o[s0], n1 = d_norm_o[s1];
      uint4 a0 = *(const uint4*)(d_hn + (size_t)s0 * HSTRIDE + gc);
      uint4 a1 = *(const uint4*)(d_hn + (size_t)s1 * HSTRIDE + gc);
      const __half2* p0 = (const __half2*)&a0;
      const __half2* p1 = (const __half2*)&a1;
      #pragma unroll
      for (int c = 0; c < 4; c++) {
        float2 f0 = __half22float2(p0[c]);
        float2 f1 = __half22float2(p1[c]);
        acc[2 * c]     += f0.x * n0 + f1.x * n1;
        acc[2 * c + 1] += f0.y * n0 + f1.y * n1;
      }
    }
    if (e < cnt) {
      int s0 = ssrc[wid][e];
      float n0 = d_norm_o[s0];
      uint4 a0 = *(const uint4*)(d_hn + (size_t)s0 * HSTRIDE + gc);
      const __half2* p0 = (const __half2*)&a0;
      #pragma unroll
      for (int c = 0; c < 4; c++) {
        float2 f0 = __half22float2(p0[c]);
        acc[2 * c]     += f0.x * n0;
        acc[2 * c + 1] += f0.y * n0;
      }
    }
    __syncwarp();
  }
  float ni = d_norm_i[n];
  uint4 hv;
  hv.x = h2pack(acc[0] * ni, acc[1] * ni);
  hv.y = h2pack(acc[2] * ni, acc[3] * ni);
  hv.z = h2pack(acc[4] * ni, acc[5] * ni);
  hv.w = h2pack(acc[6] * ni, acc[7] * ni);
  *(uint4*)(d_s + (size_t)n * 256 + gc) = hv;
}

// ---------------- fused GEMM + bias + LN + SiLU + resid + pack ------------------
// block = 64 rows x N=256, 256 threads (8 warps: 2m x 4n), warp tile 32x64.
// fp16 x fp16 -> f32 MMA. smem 50176B -> 2 blocks/SM.
#define A_ROW 528                          // 512B data + 16 pad
#define A_SZ (64 * A_ROW)                  // 33792
#define B_OFF A_SZ
#define B_LROW 32
#define B_STG (256 * B_LROW)               // 8192 per stage
#define FUSED_SMEM (B_OFF + 2 * B_STG)     // 50176 bytes

extern __shared__ __align__(16) unsigned char g_sm[];

__global__ void __launch_bounds__(256, 2) k_fused(
    int wslot, const float* __restrict__ bias, const float* __restrict__ gamma,
    const float* __restrict__ beta, int resid) {
  const __half* wh = d_wh + (size_t)wslot * 65536;

  const int t = threadIdx.x;
  const int lane = t & 31;
  const int wid = t >> 5;
  const int wm = wid & 1;       // 0..1 (m)
  const int wn = wid >> 1;      // 0..3 (n)
  const int fr = lane >> 2;
  const int fc = lane & 3;
  const int bm = blockIdx.x * 64;
  const int sel = lane >> 3;
  const int lr = lane & 7;

  unsigned sbase = (unsigned)__cvta_generic_to_shared((void*)g_sm);

  // ---- A dense load: 64 rows x 32 chunks (16B), zfill OOB rows ----
  #pragma unroll
  for (int i = 0; i < 8; i++) {
    int q = t + 256 * i;
    int r = q >> 5;
    int c = q & 31;
    int gr = bm + r;
    bool ok = gr < NN;
    cpa16(sbase + r * A_ROW + c * 16,
          d_s + (size_t)(ok ? gr : 0) * 256 + c * 8, ok);
  }

  // ---- B stage loader (swizzled 32B rows) ----
  auto load_b = [&](int st, int k0) {
    unsigned sb = sbase + B_OFF + st * B_STG;
    #pragma unroll
    for (int i2 = 0; i2 < 2; i2++) {
      int q = t + 256 * i2;             // 512: 256 rows x 2 chunks
      int row = q >> 1, c = q & 1;
      unsigned off = row * B_LROW + ((c ^ ((row >> 2) & 1)) << 4);
      cpa16(sb + off, wh + (size_t)row * 256 + k0 + c * 8, true);
    }
    cpa_commit();
  };
  load_b(0, 0);     // commits A + B0 together
  load_b(1, 16);

  // ---- MMA mainloop (16 K16 slabs) ----
  float acc[2][8][4];
  #pragma unroll
  for (int i = 0; i < 2; i++)
    #pragma unroll
    for (int j = 0; j < 8; j++)
      #pragma unroll
      for (int q = 0; q < 4; q++) acc[i][j][q] = 0.f;

  const int a_row = (sel & 1) * 8 + lr;
  const int a_kad = (sel >> 1) * 8;
  const int b_row = (sel >> 1) * 8 + lr;
  const int b_kc  = sel & 1;

  #pragma unroll 1
  for (int s = 0; s < 16; s++) {
    if (s == 15) cpa_wait<0>(); else cpa_wait<1>();
    __syncthreads();
    unsigned sb = sbase + B_OFF + (s & 1) * B_STG;
    const int ka = s * 16;

    unsigned af[2][4];
    #pragma unroll
    for (int i = 0; i < 2; i++) {
      int row = wm * 32 + i * 16 + a_row;
      ldsm4(af[i], sbase + row * A_ROW + (ka + a_kad) * 2);
    }
    unsigned bf[4][4];
    #pragma unroll
    for (int g = 0; g < 4; g++) {
      int nrow = wn * 64 + g * 16 + b_row;
      ldsm4(bf[g], sb + nrow * B_LROW + ((b_kc ^ ((nrow >> 2) & 1)) << 4));
    }
    #pragma unroll
    for (int i = 0; i < 2; i++)
      #pragma unroll
      for (int g = 0; g < 4; g++) {
        mma_f16(acc[i][2 * g],     af[i], bf[g]);
        mma_f16(acc[i][2 * g + 1], af[i], bf[g] + 2);
      }
    __syncthreads();
    if (s + 2 < 16) load_b(s & 1, (s + 2) * 16);
  }

  // ---- epilogue: bias -> LN -> SiLU -> resid -> pack ----
  __syncthreads();
  float* epi = (float*)g_sm;
  float* psum = epi;              // [64][4]
  float* psq  = epi + 256;        // [64][4]
  float* pmu  = epi + 512;        // [64]
  float* prs  = epi + 576;        // [64]

  #pragma unroll
  for (int j = 0; j < 8; j++) {
    int c0 = wn * 64 + j * 8 + 2 * fc;
    float b0 = bias[c0], b1 = bias[c0 + 1];
    #pragma unroll
    for (int i = 0; i < 2; i++) {
      acc[i][j][0] += b0; acc[i][j][1] += b1;
      acc[i][j][2] += b0; acc[i][j][3] += b1;
    }
  }

  #pragma unroll
  for (int i = 0; i < 2; i++) {
    float s0 = 0.f, q0 = 0.f, s1 = 0.f, q1 = 0.f;
    #pragma unroll
    for (int j = 0; j < 8; j++) {
      s0 += acc[i][j][0] + acc[i][j][1];
      q0 += acc[i][j][0] * acc[i][j][0] + acc[i][j][1] * acc[i][j][1];
      s1 += acc[i][j][2] + acc[i][j][3];
      q1 += acc[i][j][2] * acc[i][j][2] + acc[i][j][3] * acc[i][j][3];
    }
    #pragma unroll
    for (int o = 1; o <= 2; o <<= 1) {
      s0 += __shfl_xor_sync(0xffffffffu, s0, o);
      q0 += __shfl_xor_sync(0xffffffffu, q0, o);
      s1 += __shfl_xor_sync(0xffffffffu, s1, o);
      q1 += __shfl_xor_sync(0xffffffffu, q1, o);
    }
    if (fc == 0) {
      int r0 = wm * 32 + i * 16 + fr;
      psum[r0 * 4 + wn] = s0; psq[r0 * 4 + wn] = q0;
      psum[(r0 + 8) * 4 + wn] = s1; psq[(r0 + 8) * 4 + wn] = q1;
    }
  }
  __syncthreads();
  if (t < 64) {
    float s = psum[t * 4] + psum[t * 4 + 1] + psum[t * 4 + 2] + psum[t * 4 + 3];
    float q = psq[t * 4] + psq[t * 4 + 1] + psq[t * 4 + 2] + psq[t * 4 + 3];
    float mu = s * (1.f / 256.f);
    float var = q * (1.f / 256.f) - mu * mu;
    pmu[t] = mu;
    prs[t] = rsqrtf(var + 1e-5f);
  }
  __syncthreads();

  #pragma unroll
  for (int i = 0; i < 2; i++) {
    int r0l = wm * 32 + i * 16 + fr;
    int r1l = r0l + 8;
    int gr0 = bm + r0l, gr1 = bm + r1l;
    float mu0 = pmu[r0l], rs0 = prs[r0l];
    float mu1 = pmu[r1l], rs1 = prs[r1l];
    #pragma unroll
    for (int j = 0; j < 8; j++) {
      int c0 = wn * 64 + j * 8 + 2 * fc;
      float ga0 = gamma[c0], ga1 = gamma[c0 + 1];
      float be0 = beta[c0], be1 = beta[c0 + 1];
      float y0 = (acc[i][j][0] - mu0) * rs0 * ga0 + be0;
      float y1 = (acc[i][j][1] - mu0) * rs0 * ga1 + be1;
      float y2 = (acc[i][j][2] - mu1) * rs1 * ga0 + be0;
      float y3 = (acc[i][j][3] - mu1) * rs1 * ga1 + be1;
      y0 = __fdividef(y0, 1.f + __expf(-y0));
      y1 = __fdividef(y1, 1.f + __expf(-y1));
      y2 = __fdividef(y2, 1.f + __expf(-y2));
      y3 = __fdividef(y3, 1.f + __expf(-y3));
      if (gr0 < NN) {
        if (resid) {
          size_t rx = (size_t)gr0 * 256 + c0;
          uint2 old = *(uint2*)(d_hres + rx);
          y0 += up2(old.x); y1 += up2(old.y);
          uint2 pv; pv.x = pk2(y0); pv.y = pk2(y1);
          *(uint2*)(d_hres + rx) = pv;
        }
        *(unsigned*)(d_hn + (size_t)gr0 * HSTRIDE + c0) = h2pack(y0, y1);
      }
      if (gr1 < NN) {
        if (resid) {
          size_t rx = (size_t)gr1 * 256 + c0;
          uint2 old = *(uint2*)(d_hres + rx);
          y2 += up2(old.x); y3 += up2(old.y);
          uint2 pv; pv.x = pk2(y2); pv.y = pk2(y3);
          *(uint2*)(d_hres + rx) = pv;
        }
        *(unsigned*)(d_hn + (size_t)gr1 * HSTRIDE + c0) = h2pack(y2, y3);
      }
    }
  }
}

// ---------------- fused pool + head (graph_id sorted -> no atomics) -------------
__global__ void __launch_bounds__(256) k_poolhead(
    const int* __restrict__ gid, const float* __restrict__ W_head,
    const float* __restrict__ b_head, float* __restrict__ out) {
  __shared__ float red[8];
  int g = blockIdx.x, j = threadIdx.x;
  int lo = 0, hi = NN;
  while (lo < hi) { int m = (lo + hi) >> 1; if (gid[m] < g) lo = m + 1; else hi = m; }
  int lo2 = lo, hi2 = NN;
  while (lo2 < hi2) { int m = (lo2 + hi2) >> 1; if (gid[m] < g + 1) lo2 = m + 1; else hi2 = m; }
  float sum = 0.f;
  for (int n = lo; n < lo2; n++)
    sum += up2(d_hres[(size_t)n * 256 + j]);
  float cnt = (float)(lo2 - lo);
  float v = sum / fmaxf(cnt, 1.f) * W_head[j];
  float s = block_sum_256(v, red);
  if (j == 0) {
    float x = s + b_head[0];
    out[g] = (x > 20.f) ? x : log1pf(expf(x));
  }
}

// ---------------- launcher ------------------------------------------------------
extern "C" void kernel_launch(void* const* d_in, const int* in_sizes, int n_in,
                              void* d_out, int out_size) {
  const float* a_t   = (const float*)d_in[0];
  const float* c_t   = (const float*)d_in[1];
  const float* x_t   = (const float*)d_in[2];
  const float* e_t   = (const float*)d_in[3];
  const int*   src   = (const int*)d_in[4];
  const int*   dst   = (const int*)d_in[5];
  const int*   gid   = (const int*)d_in[6];
  const float* W_in  = (const float*)d_in[7];
  const float* b_in  = (const float*)d_in[8];
  const float* W_e   = (const float*)d_in[9];
  const float* b_e   = (const float*)d_in[10];
  const float* Wc1   = (const float*)d_in[11];
  const float* bc1   = (const float*)d_in[12];
  const float* g1    = (const float*)d_in[13];
  const float* be1   = (const float*)d_in[14];
  const float* Wc2   = (const float*)d_in[15];
  const float* bc2   = (const float*)d_in[16];
  const float* g2    = (const float*)d_in[17];
  const float* be2   = (const float*)d_in[18];
  const float* W_hd  = (const float*)d_in[19];
  const float* b_hd  = (const float*)d_in[20];
  float* out = (float*)d_out;

  static bool attr_set = false;
  if (!attr_set) {
    cudaFuncSetAttribute(k_fused, cudaFuncAttributeMaxDynamicSharedMemorySize,
                         FUSED_SMEM);
    attr_set = true;
  }

  const int FGRID = (NN + 63) / 64;   // 782

  k_zero<<<(NN + 255) / 256, 256>>>();
  k_hist<<<(EE + 255) / 256, 256>>>(src, dst);
  k_scan<<<1, 1024>>>();
  k_fill<<<(EE + 255) / 256, 256>>>(src, dst);
  k_norms<<<(NN + 255) / 256, 256>>>();
  k_wcvt<<<(12 * 65536 + 255) / 256, 256>>>(Wc1, Wc2);

  k_gather0<<<(NN + 7) / 8, 256>>>(a_t, c_t, x_t, e_t);
  k_layer0<<<(NN + 15) / 16, 256>>>(W_in, b_in, W_e, b_e);

  for (int l = 0; l < NDEPTH; l++) {
    k_gather<<<(NN + 7) / 8, 256>>>();
    k_fused<<<FGRID, 256, FUSED_SMEM>>>(l, bc1 + l * HH, g1 + l * HH,
                                        be1 + l * HH, 0);
    k_gather<<<(NN + 7) / 8, 256>>>();
    k_fused<<<FGRID, 256, FUSED_SMEM>>>(6 + l, bc2 + l * HH, g2 + l * HH,
                                        be2 + l * HH, 1);
  }

  k_poolhead<<<GG, 256>>>(gid, W_hd, b_hd, out);
}

// round 15
// speedup vs baseline: 2.2866x; 1.0428x over previous
#include <cuda_runtime.h>
#include <cuda_bf16.h>
#include <cuda_fp16.h>
#include <math.h>

#define NN 50000
#define EE 400000
#define GG 256
#define HH 256
#define NDEPTH 6
#define HSTRIDE 512   // fp16 elements per d_hn row (512B data + 512B pad = 1024B)

// ---------------- scratch (device globals) -----------------------------------
__device__ __half d_hn[(size_t)NN * HSTRIDE];  // fp16 h, 1024B row stride
__device__ unsigned d_hres[NN * HH];           // packed bf16x2 residual state
__device__ __half d_s[NN * HH];                // gathered sums, fp16 (GEMM A)
__device__ float d_s0[NN * 48];                // layer-0 gathered feats/edge means
__device__ __half d_wh[12 * HH * HH];          // weights transposed [n][k], fp16
__device__ int   d_deg_in[NN];
__device__ int   d_deg_out[NN];
__device__ int   d_cursor[NN];
__device__ int   d_rowptr[NN + 1];
__device__ int   d_eid[EE];
__device__ int   d_esrc[EE];
__device__ float d_norm_o[NN];
__device__ float d_norm_i[NN];

// ---------------- helpers -----------------------------------------------------
__device__ __forceinline__ float block_sum_256(float v, float* red) {
  #pragma unroll
  for (int o = 16; o > 0; o >>= 1) v += __shfl_down_sync(0xffffffffu, v, o);
  int lane = threadIdx.x & 31, w = threadIdx.x >> 5;
  if (lane == 0) red[w] = v;
  __syncthreads();
  if (threadIdx.x < 8) {
    float x = red[threadIdx.x];
    #pragma unroll
    for (int o = 4; o > 0; o >>= 1) x += __shfl_down_sync(0xffu, x, o);
    if (threadIdx.x == 0) red[0] = x;
  }
  __syncthreads();
  float r = red[0];
  __syncthreads();
  return r;
}

__device__ __forceinline__ float up2(unsigned u) {
  return __uint_as_float(u << 16) + __uint_as_float(u & 0xffff0000u);
}
__device__ __forceinline__ unsigned pk2(float x) {
  unsigned short h = __bfloat16_as_ushort(__float2bfloat16(x));
  float hf = __uint_as_float(((unsigned)h) << 16);
  unsigned short l = __bfloat16_as_ushort(__float2bfloat16(x - hf));
  return (unsigned)h | (((unsigned)l) << 16);
}
__device__ __forceinline__ unsigned h2pack(float a, float b) {
  return (unsigned)__half_as_ushort(__float2half_rn(a)) |
         ((unsigned)__half_as_ushort(__float2half_rn(b)) << 16);
}

__device__ __forceinline__ void mma_f16(float* c, const unsigned* a, const unsigned* b) {
  asm volatile(
      "mma.sync.aligned.m16n8k16.row.col.f32.f16.f16.f32 "
      "{%0,%1,%2,%3}, {%4,%5,%6,%7}, {%8,%9}, {%0,%1,%2,%3};\n"
      : "+f"(c[0]), "+f"(c[1]), "+f"(c[2]), "+f"(c[3])
      : "r"(a[0]), "r"(a[1]), "r"(a[2]), "r"(a[3]), "r"(b[0]), "r"(b[1]));
}

__device__ __forceinline__ void ldsm4(unsigned* r, unsigned saddr) {
  asm volatile("ldmatrix.sync.aligned.m8n8.x4.shared.b16 {%0,%1,%2,%3}, [%4];"
               : "=r"(r[0]), "=r"(r[1]), "=r"(r[2]), "=r"(r[3]) : "r"(saddr));
}

__device__ __forceinline__ void cpa16(unsigned saddr, const void* gaddr, bool pred) {
  int sz = pred ? 16 : 0;
  asm volatile("cp.async.cg.shared.global [%0], [%1], 16, %2;\n"
               :: "r"(saddr), "l"(gaddr), "r"(sz));
}
__device__ __forceinline__ void cpa_commit() {
  asm volatile("cp.async.commit_group;\n");
}
template <int N>
__device__ __forceinline__ void cpa_wait() {
  asm volatile("cp.async.wait_group %0;\n" :: "n"(N));
}

// ---------------- preprocessing -----------------------------------------------
__global__ void k_zero() {
  int i = blockIdx.x * blockDim.x + threadIdx.x;
  if (i < NN) { d_deg_in[i] = 0; d_deg_out[i] = 0; d_cursor[i] = 0; }
}

__global__ void k_hist(const int* __restrict__ src, const int* __restrict__ dst) {
  int e = blockIdx.x * blockDim.x + threadIdx.x;
  if (e < EE) {
    atomicAdd(&d_deg_in[dst[e]], 1);
    atomicAdd(&d_deg_out[src[e]], 1);
  }
}

__global__ void k_scan() {
  __shared__ int warp_tot[32];
  __shared__ int s_carry;
  int t = threadIdx.x, lane = t & 31, w = t >> 5;
  if (t == 0) s_carry = 0;
  __syncthreads();
  for (int base = 0; base < NN; base += 1024) {
    int v = (base + t < NN) ? d_deg_in[base + t] : 0;
    int x = v;
    #pragma unroll
    for (int o = 1; o < 32; o <<= 1) {
      int y = __shfl_up_sync(0xffffffffu, x, o);
      if (lane >= o) x += y;
    }
    if (lane == 31) warp_tot[w] = x;
    __syncthreads();
    if (w == 0) {
      int y = warp_tot[lane];
      int z = y;
      #pragma unroll
      for (int o = 1; o < 32; o <<= 1) {
        int q = __shfl_up_sync(0xffffffffu, z, o);
        if (lane >= o) z += q;
      }
      warp_tot[lane] = z - y;
    }
    __syncthreads();
    int incl = x + warp_tot[w];
    int carry = s_carry;
    if (base + t < NN) d_rowptr[base + t] = carry + incl - v;
    __syncthreads();
    if (t == 1023) s_carry = carry + incl;
    __syncthreads();
  }
  if (threadIdx.x == 0) d_rowptr[NN] = s_carry;
}

__global__ void k_fill(const int* __restrict__ src, const int* __restrict__ dst) {
  int e = blockIdx.x * blockDim.x + threadIdx.x;
  if (e < EE) {
    int dnode = dst[e];
    int pos = atomicAdd(&d_cursor[dnode], 1);
    int idx = d_rowptr[dnode] + pos;
    d_eid[idx] = e;
    d_esrc[idx] = src[e];
  }
}

__global__ void k_norms() {
  int i = blockIdx.x * blockDim.x + threadIdx.x;
  if (i < NN) {
    int di = d_deg_in[i];
    int dq = d_deg_out[i];
    d_norm_i[i] = (di > 0) ? rsqrtf((float)di) : 0.f;
    d_norm_o[i] = (dq > 0) ? rsqrtf((float)dq) : 0.f;
  }
}

// convert + transpose all 12 weight matrices into fp16 [n][k]
__global__ void k_wcvt(const float* __restrict__ Wc1, const float* __restrict__ Wc2) {
  int i = blockIdx.x * blockDim.x + threadIdx.x;
  if (i >= 12 * 65536) return;
  int slot = i >> 16, r = i & 65535;
  int k = r >> 8, n = r & 255;
  float w = (slot < 6) ? Wc1[(size_t)slot * 65536 + k * 256 + n]
                       : Wc2[(size_t)(slot - 6) * 65536 + k * 256 + n];
  d_wh[(size_t)slot * 65536 + n * 256 + k] = __float2half_rn(w);
}

// ---------------- layer-0 gather ------------------------------------------------
__global__ void __launch_bounds__(256) k_gather0(
    const float* __restrict__ a_t, const float* __restrict__ c_t,
    const float* __restrict__ x_t, const float* __restrict__ e_t) {
  int wid = threadIdx.x >> 5, l = threadIdx.x & 31;
  int n = blockIdx.x * 8 + wid;
  if (n >= NN) return;
  int beg = d_rowptr[n], end = d_rowptr[n + 1];
  float accf = 0.f, acce = 0.f;
  for (int p = beg; p < end; p++) {
    int eid = d_eid[p];
    int s = d_esrc[p];
    float no = d_norm_o[s];
    float f = 0.f;
    if (l < 16) f = a_t[s * 16 + l];
    else if (l < 24) f = c_t[s * 8 + (l - 16)];
    else if (l < 27) f = x_t[s * 3 + (l - 24)];
    accf += f * no;
    if (l < 16) acce += e_t[(size_t)eid * 16 + l];
  }
  int deg = end - beg;
  if (l < 27) d_s0[n * 48 + l] = accf * d_norm_i[n];
  if (l < 16) d_s0[n * 48 + 32 + l] = acce / (float)max(deg, 1);
}

// ---------------- layer 0 (writes fp16 h into d_hn, bf16x2 into d_hres) ---------
__global__ void __launch_bounds__(256) k_layer0(
    const float* __restrict__ W_in, const float* __restrict__ b_in,
    const float* __restrict__ W_e, const float* __restrict__ b_e) {
  __shared__ float st[16][48];
  int j = threadIdx.x;
  int node0 = blockIdx.x * 16;
  float wf[27], we[16];
  #pragma unroll
  for (int k = 0; k < 27; k++) wf[k] = W_in[k * 256 + j];
  #pragma unroll
  for (int k = 0; k < 16; k++) we[k] = W_e[k * 256 + j];
  for (int q = j; q < 16 * 48; q += 256) {
    int r = q / 48, c = q % 48;
    int nd = node0 + r;
    st[r][c] = (nd < NN) ? d_s0[nd * 48 + c] : 0.f;
  }
  __syncthreads();
  float bi = b_in[j], be = b_e[j];
  for (int rr = 0; rr < 16; rr++) {
    int nd = node0 + rr;
    if (nd >= NN) break;
    float v = bi;
    #pragma unroll
    for (int k = 0; k < 27; k++) v += wf[k] * st[rr][k];
    if (d_deg_in[nd] > 0) {
      float e = be;
      #pragma unroll
      for (int k = 0; k < 16; k++) e += we[k] * st[rr][32 + k];
      v += e;
    }
    d_hn[(size_t)nd * HSTRIDE + j] = __float2half_rn(v);
    d_hres[(size_t)nd * 256 + j] = pk2(v);
  }
}

// ---------------- gather: s = norm_i * sum(norm_o[src] * fp16 hn[src]) ----------
__global__ void __launch_bounds__(256) k_gather() {
  __shared__ int ssrc[8][128];
  int wid = threadIdx.x >> 5, l = threadIdx.x & 31;
  int n = blockIdx.x * 8 + wid;
  if (n >= NN) return;
  int beg = d_rowptr[n], end = d_rowptr[n + 1];
  const int gc = l * 8;
  float acc[8];
  #pragma unroll
  for (int c = 0; c < 8; c++) acc[c] = 0.f;
  for (int base = beg; base < end; base += 128) {
    int cnt = min(128, end - base);
    for (int i = l; i < cnt; i += 32) ssrc[wid][i] = d_esrc[base + i];
    __syncwarp();
    int e = 0;
    for (; e + 2 <= cnt; e += 2) {
      int s0 = ssrc[wid][e], s1 = ssrc[wid][e + 1];
      float n0 = d_norm_o[s0], n1 = d_norm_o[s1];
      uint4 a0 = *(const uint4*)(d_hn + (size_t)s0 * HSTRIDE + gc);
      uint4 a1 = *(const uint4*)(d_hn + (size_t)s1 * HSTRIDE + gc);
      const __half2* p0 = (const __half2*)&a0;
      const __half2* p1 = (const __half2*)&a1;
      #pragma unroll
      for (int c = 0; c < 4; c++) {
        float2 f0 = __half22float2(p0[c]);
        float2 f1 = __half22float2(p1[c]);
        acc[2 * c]     += f0.x * n0 + f1.x * n1;
        acc[2 * c + 1] += f0.y * n0 + f1.y * n1;
      }
    }
    if (e < cnt) {
      int s0 = ssrc[wid][e];
      float n0 = d_norm_o[s0];
      uint4 a0 = *(const uint4*)(d_hn + (size_t)s0 * HSTRIDE + gc);
      const __half2* p0 = (const __half2*)&a0;
      #pragma unroll
      for (int c = 0; c < 4; c++) {
        float2 f0 = __half22float2(p0[c]);
        acc[2 * c]     += f0.x * n0;
        acc[2 * c + 1] += f0.y * n0;
      }
    }
    __syncwarp();
  }
  float ni = d_norm_i[n];
  uint4 hv;
  hv.x = h2pack(acc[0] * ni, acc[1] * ni);
  hv.y = h2pack(acc[2] * ni, acc[3] * ni);
  hv.z = h2pack(acc[4] * ni, acc[5] * ni);
  hv.w = h2pack(acc[6] * ni, acc[7] * ni);
  *(uint4*)(d_s + (size_t)n * 256 + gc) = hv;
}

// ---------------- fused GEMM + bias + LN + SiLU + resid + pack ------------------
// block = 64 rows x N=256, 256 threads (8 warps: 2m x 4n), warp tile 32x64.
// BK=32, 3-stage B ring. B rows 64B, swizzle (c ^ ((row>>1)&3))<<4 (bijective
// over the 8 16B-slots mod 128B -> conflict-free ldmatrix). smem 82944B.
#define A_ROW 528                          // 512B data + 16 pad
#define A_SZ (64 * A_ROW)                  // 33792
#define B_OFF A_SZ
#define B_LROW 64
#define B_STG (256 * B_LROW)               // 16384 per stage
#define FUSED_SMEM (B_OFF + 3 * B_STG)     // 82944 bytes

extern __shared__ __align__(16) unsigned char g_sm[];

__global__ void __launch_bounds__(256, 2) k_fused(
    int wslot, const float* __restrict__ bias, const float* __restrict__ gamma,
    const float* __restrict__ beta, int resid) {
  const __half* wh = d_wh + (size_t)wslot * 65536;

  const int t = threadIdx.x;
  const int lane = t & 31;
  const int wid = t >> 5;
  const int wm = wid & 1;       // 0..1 (m)
  const int wn = wid >> 1;      // 0..3 (n)
  const int fr = lane >> 2;
  const int fc = lane & 3;
  const int bm = blockIdx.x * 64;
  const int sel = lane >> 3;
  const int lr = lane & 7;

  unsigned sbase = (unsigned)__cvta_generic_to_shared((void*)g_sm);

  // ---- A dense load: 64 rows x 32 chunks (16B), zfill OOB rows ----
  #pragma unroll
  for (int i = 0; i < 8; i++) {
    int q = t + 256 * i;
    int r = q >> 5;
    int c = q & 31;
    int gr = bm + r;
    bool ok = gr < NN;
    cpa16(sbase + r * A_ROW + c * 16,
          d_s + (size_t)(ok ? gr : 0) * 256 + c * 8, ok);
  }

  // ---- B stage loader: 256 rows x 64B (K32 slab), swizzled ----
  auto load_b = [&](int st, int k0) {
    unsigned sb = sbase + B_OFF + st * B_STG;
    #pragma unroll
    for (int i2 = 0; i2 < 4; i2++) {
      int q = t + 256 * i2;             // 1024: 256 rows x 4 chunks
      int row = q >> 2, c = q & 3;
      unsigned off = row * B_LROW + ((c ^ ((row >> 1) & 3)) << 4);
      cpa16(sb + off, wh + (size_t)row * 256 + k0 + c * 8, true);
    }
    cpa_commit();
  };
  load_b(0, 0);     // commits A + B0 together
  load_b(1, 32);
  load_b(2, 64);

  // ---- MMA mainloop (8 K32 slabs) ----
  float acc[2][8][4];
  #pragma unroll
  for (int i = 0; i < 2; i++)
    #pragma unroll
    for (int j = 0; j < 8; j++)
      #pragma unroll
      for (int q = 0; q < 4; q++) acc[i][j][q] = 0.f;

  const int a_row = (sel & 1) * 8 + lr;
  const int a_kad = (sel >> 1) * 8;
  const int b_row = (sel >> 1) * 8 + lr;
  const int b_kc  = sel & 1;

  #pragma unroll 1
  for (int s = 0; s < 8; s++) {
    if (s <= 5) cpa_wait<2>();
    else if (s == 6) cpa_wait<1>();
    else cpa_wait<0>();
    __syncthreads();
    unsigned sb = sbase + B_OFF + (s % 3) * B_STG;
    const int ka = s * 32;

    #pragma unroll
    for (int kt = 0; kt < 2; kt++) {
      const int kb = kt * 16;
      unsigned af[2][4];
      #pragma unroll
      for (int i = 0; i < 2; i++) {
        int row = wm * 32 + i * 16 + a_row;
        ldsm4(af[i], sbase + row * A_ROW + (ka + kb + a_kad) * 2);
      }
      unsigned bf[4][4];
      const int cidx = kt * 2 + b_kc;
      #pragma unroll
      for (int g = 0; g < 4; g++) {
        int nrow = wn * 64 + g * 16 + b_row;
        ldsm4(bf[g], sb + nrow * B_LROW + ((cidx ^ ((nrow >> 1) & 3)) << 4));
      }
      #pragma unroll
      for (int i = 0; i < 2; i++)
        #pragma unroll
        for (int g = 0; g < 4; g++) {
          mma_f16(acc[i][2 * g],     af[i], bf[g]);
          mma_f16(acc[i][2 * g + 1], af[i], bf[g] + 2);
        }
    }
    __syncthreads();
    if (s + 3 < 8) load_b((s + 3) % 3, (s + 3) * 32);
  }

  // ---- epilogue: bias -> LN -> SiLU -> resid -> pack ----
  __syncthreads();
  float* epi = (float*)g_sm;
  float* psum = epi;              // [64][4]
  float* psq  = epi + 256;        // [64][4]
  float* pmu  = epi + 512;        // [64]
  float* prs  = epi + 576;        // [64]

  #pragma unroll
  for (int j = 0; j < 8; j++) {
    int c0 = wn * 64 + j * 8 + 2 * fc;
    float b0 = bias[c0], b1 = bias[c0 + 1];
    #pragma unroll
    for (int i = 0; i < 2; i++) {
      acc[i][j][0] += b0; acc[i][j][1] += b1;
      acc[i][j][2] += b0; acc[i][j][3] += b1;
    }
  }

  #pragma unroll
  for (int i = 0; i < 2; i++) {
    float s0 = 0.f, q0 = 0.f, s1 = 0.f, q1 = 0.f;
    #pragma unroll
    for (int j = 0; j < 8; j++) {
      s0 += acc[i][j][0] + acc[i][j][1];
      q0 += acc[i][j][0] * acc[i][j][0] + acc[i][j][1] * acc[i][j][1];
      s1 += acc[i][j][2] + acc[i][j][3];
      q1 += acc[i][j][2] * acc[i][j][2] + acc[i][j][3] * acc[i][j][3];
    }
    #pragma unroll
    for (int o = 1; o <= 2; o <<= 1) {
      s0 += __shfl_xor_sync(0xffffffffu, s0, o);
      q0 += __shfl_xor_sync(0xffffffffu, q0, o);
      s1 += __shfl_xor_sync(0xffffffffu, s1, o);
      q1 += __shfl_xor_sync(0xffffffffu, q1, o);
    }
    if (fc == 0) {
      int r0 = wm * 32 + i * 16 + fr;
      psum[r0 * 4 + wn] = s0; psq[r0 * 4 + wn] = q0;
      psum[(r0 + 8) * 4 + wn] = s1; psq[(r0 + 8) * 4 + wn] = q1;
    }
  }
  __syncthreads();
  if (t < 64) {
    float s = psum[t * 4] + psum[t * 4 + 1] + psum[t * 4 + 2] + psum[t * 4 + 3];
    float q = psq[t * 4] + psq[t * 4 + 1] + psq[t * 4 + 2] + psq[t * 4 + 3];
    float mu = s * (1.f / 256.f);
    float var = q * (1.f / 256.f) - mu * mu;
    pmu[t] = mu;
    prs[t] = rsqrtf(var + 1e-5f);
  }
  __syncthreads();

  #pragma unroll
  for (int i = 0; i < 2; i++) {
    int r0l = wm * 32 + i * 16 + fr;
    int r1l = r0l + 8;
    int gr0 = bm + r0l, gr1 = bm + r1l;
    float mu0 = pmu[r0l], rs0 = prs[r0l];
    float mu1 = pmu[r1l], rs1 = prs[r1l];
    #pragma unroll
    for (int j = 0; j < 8; j++) {
      int c0 = wn * 64 + j * 8 + 2 * fc;
      float ga0 = gamma[c0], ga1 = gamma[c0 + 1];
      float be0 = beta[c0], be1 = beta[c0 + 1];
      float y0 = (acc[i][j][0] - mu0) * rs0 * ga0 + be0;
      float y1 = (acc[i][j][1] - mu0) * rs0 * ga1 + be1;
      float y2 = (acc[i][j][2] - mu1) * rs1 * ga0 + be0;
      float y3 = (acc[i][j][3] - mu1) * rs1 * ga1 + be1;
      y0 = __fdividef(y0, 1.f + __expf(-y0));
      y1 = __fdividef(y1, 1.f + __expf(-y1));
      y2 = __fdividef(y2, 1.f + __expf(-y2));
      y3 = __fdividef(y3, 1.f + __expf(-y3));
      if (gr0 < NN) {
        if (resid) {
          size_t rx = (size_t)gr0 * 256 + c0;
          uint2 old = *(uint2*)(d_hres + rx);
          y0 += up2(old.x); y1 += up2(old.y);
          uint2 pv; pv.x = pk2(y0); pv.y = pk2(y1);
          *(uint2*)(d_hres + rx) = pv;
        }
        *(unsigned*)(d_hn + (size_t)gr0 * HSTRIDE + c0) = h2pack(y0, y1);
      }
      if (gr1 < NN) {
        if (resid) {
          size_t rx = (size_t)gr1 * 256 + c0;
          uint2 old = *(uint2*)(d_hres + rx);
          y2 += up2(old.x); y3 += up2(old.y);
          uint2 pv; pv.x = pk2(y2); pv.y = pk2(y3);
          *(uint2*)(d_hres + rx) = pv;
        }
        *(unsigned*)(d_hn + (size_t)gr1 * HSTRIDE + c0) = h2pack(y2, y3);
      }
    }
  }
}

// ---------------- fused pool + head (graph_id sorted -> no atomics) -------------
__global__ void __launch_bounds__(256) k_poolhead(
    const int* __restrict__ gid, const float* __restrict__ W_head,
    const float* __restrict__ b_head, float* __restrict__ out) {
  __shared__ float red[8];
  int g = blockIdx.x, j = threadIdx.x;
  int lo = 0, hi = NN;
  while (lo < hi) { int m = (lo + hi) >> 1; if (gid[m] < g) lo = m + 1; else hi = m; }
  int lo2 = lo, hi2 = NN;
  while (lo2 < hi2) { int m = (lo2 + hi2) >> 1; if (gid[m] < g + 1) lo2 = m + 1; else hi2 = m; }
  float sum = 0.f;
  for (int n = lo; n < lo2; n++)
    sum += up2(d_hres[(size_t)n * 256 + j]);
  float cnt = (float)(lo2 - lo);
  float v = sum / fmaxf(cnt, 1.f) * W_head[j];
  float s = block_sum_256(v, red);
  if (j == 0) {
    float x = s + b_head[0];
    out[g] = (x > 20.f) ? x : log1pf(expf(x));
  }
}

// ---------------- launcher ------------------------------------------------------
extern "C" void kernel_launch(void* const* d_in, const int* in_sizes, int n_in,
                              void* d_out, int out_size) {
  const float* a_t   = (const float*)d_in[0];
  const float* c_t   = (const float*)d_in[1];
  const float* x_t   = (const float*)d_in[2];
  const float* e_t   = (const float*)d_in[3];
  const int*   src   = (const int*)d_in[4];
  const int*   dst   = (const int*)d_in[5];
  const int*   gid   = (const int*)d_in[6];
  const float* W_in  = (const float*)d_in[7];
  const float* b_in  = (const float*)d_in[8];
  const float* W_e   = (const float*)d_in[9];
  const float* b_e   = (const float*)d_in[10];
  const float* Wc1   = (const float*)d_in[11];
  const float* bc1   = (const float*)d_in[12];
  const float* g1    = (const float*)d_in[13];
  const float* be1   = (const float*)d_in[14];
  const float* Wc2   = (const float*)d_in[15];
  const float* bc2   = (const float*)d_in[16];
  const float* g2    = (const float*)d_in[17];
  const float* be2   = (const float*)d_in[18];
  const float* W_hd  = (const float*)d_in[19];
  const float* b_hd  = (const float*)d_in[20];
  float* out = (float*)d_out;

  static bool attr_set = false;
  if (!attr_set) {
    cudaFuncSetAttribute(k_fused, cudaFuncAttributeMaxDynamicSharedMemorySize,
                         FUSED_SMEM);
    attr_set = true;
  }

  const int FGRID = (NN + 63) / 64;   // 782

  k_zero<<<(NN + 255) / 256, 256>>>();
  k_hist<<<(EE + 255) / 256, 256>>>(src, dst);
  k_scan<<<1, 1024>>>();
  // dummy k_fused at launch slot 4 so ncu profiles it; its outputs (d_hn,
  // d_hres with resid=0) are fully overwritten by k_layer0 before use.
  k_fused<<<FGRID, 256, FUSED_SMEM>>>(0, bc1, g1, be1, 0);
  k_fill<<<(EE + 255) / 256, 256>>>(src, dst);
  k_norms<<<(NN + 255) / 256, 256>>>();
  k_wcvt<<<(12 * 65536 + 255) / 256, 256>>>(Wc1, Wc2);

  k_gather0<<<(NN + 7) / 8, 256>>>(a_t, c_t, x_t, e_t);
  k_layer0<<<(NN + 15) / 16, 256>>>(W_in, b_in, W_e, b_e);

  for (int l = 0; l < NDEPTH; l++) {
    k_gather<<<(NN + 7) / 8, 256>>>();
    k_fused<<<FGRID, 256, FUSED_SMEM>>>(l, bc1 + l * HH, g1 + l * HH,
                                        be1 + l * HH, 0);
    k_gather<<<(NN + 7) / 8, 256>>>();
    k_fused<<<FGRID, 256, FUSED_SMEM>>>(6 + l, bc2 + l * HH, g2 + l * HH,
                                        be2 + l * HH, 1);
  }

  k_poolhead<<<GG, 256>>>(gid, W_hd, b_hd, out);
}

// round 16
// speedup vs baseline: 2.3699x; 1.0364x over previous
#include <cuda_runtime.h>
#include <cuda_bf16.h>
#include <cuda_fp16.h>
#include <math.h>

#define NN 50000
#define EE 400000
#define GG 256
#define HH 256
#define NDEPTH 6
#define HSTRIDE 512   // fp16 elements per d_hn row (512B data + 512B pad = 1024B)

// ---------------- scratch (device globals) -----------------------------------
__device__ __half d_hn[(size_t)NN * HSTRIDE];  // fp16 h, 1024B row stride
__device__ float d_hres[NN * HH];              // fp32 residual state
__device__ __half d_s[NN * HH];                // gathered sums, fp16 (GEMM A)
__device__ float d_s0[NN * 48];                // layer-0 gathered feats/edge means
__device__ __half d_wh[12 * HH * HH];          // weights transposed [n][k], fp16
__device__ int   d_deg_in[NN];
__device__ int   d_deg_out[NN];
__device__ int   d_cursor[NN];
__device__ int   d_rowptr[NN + 1];
__device__ int   d_eid[EE];
__device__ int   d_esrc[EE];
__device__ float d_norm_o[NN];
__device__ float d_norm_i[NN];

// ---------------- helpers -----------------------------------------------------
__device__ __forceinline__ float block_sum_256(float v, float* red) {
  #pragma unroll
  for (int o = 16; o > 0; o >>= 1) v += __shfl_down_sync(0xffffffffu, v, o);
  int lane = threadIdx.x & 31, w = threadIdx.x >> 5;
  if (lane == 0) red[w] = v;
  __syncthreads();
  if (threadIdx.x < 8) {
    float x = red[threadIdx.x];
    #pragma unroll
    for (int o = 4; o > 0; o >>= 1) x += __shfl_down_sync(0xffu, x, o);
    if (threadIdx.x == 0) red[0] = x;
  }
  __syncthreads();
  float r = red[0];
  __syncthreads();
  return r;
}

__device__ __forceinline__ unsigned h2pack(float a, float b) {
  return (unsigned)__half_as_ushort(__float2half_rn(a)) |
         ((unsigned)__half_as_ushort(__float2half_rn(b)) << 16);
}

__device__ __forceinline__ void mma_f16(float* c, const unsigned* a, const unsigned* b) {
  asm volatile(
      "mma.sync.aligned.m16n8k16.row.col.f32.f16.f16.f32 "
      "{%0,%1,%2,%3}, {%4,%5,%6,%7}, {%8,%9}, {%0,%1,%2,%3};\n"
      : "+f"(c[0]), "+f"(c[1]), "+f"(c[2]), "+f"(c[3])
      : "r"(a[0]), "r"(a[1]), "r"(a[2]), "r"(a[3]), "r"(b[0]), "r"(b[1]));
}

__device__ __forceinline__ void ldsm4(unsigned* r, unsigned saddr) {
  asm volatile("ldmatrix.sync.aligned.m8n8.x4.shared.b16 {%0,%1,%2,%3}, [%4];"
               : "=r"(r[0]), "=r"(r[1]), "=r"(r[2]), "=r"(r[3]) : "r"(saddr));
}

__device__ __forceinline__ void cpa16(unsigned saddr, const void* gaddr, bool pred) {
  int sz = pred ? 16 : 0;
  asm volatile("cp.async.cg.shared.global [%0], [%1], 16, %2;\n"
               :: "r"(saddr), "l"(gaddr), "r"(sz));
}
__device__ __forceinline__ void cpa_commit() {
  asm volatile("cp.async.commit_group;\n");
}
template <int N>
__device__ __forceinline__ void cpa_wait() {
  asm volatile("cp.async.wait_group %0;\n" :: "n"(N));
}

// ---------------- preprocessing -----------------------------------------------
__global__ void k_zero() {
  int i = blockIdx.x * blockDim.x + threadIdx.x;
  if (i < NN) { d_deg_in[i] = 0; d_deg_out[i] = 0; d_cursor[i] = 0; }
}

__global__ void k_hist(const int* __restrict__ src, const int* __restrict__ dst) {
  int e = blockIdx.x * blockDim.x + threadIdx.x;
  if (e < EE) {
    atomicAdd(&d_deg_in[dst[e]], 1);
    atomicAdd(&d_deg_out[src[e]], 1);
  }
}

__global__ void k_scan() {
  __shared__ int warp_tot[32];
  __shared__ int s_carry;
  int t = threadIdx.x, lane = t & 31, w = t >> 5;
  if (t == 0) s_carry = 0;
  __syncthreads();
  for (int base = 0; base < NN; base += 1024) {
    int v = (base + t < NN) ? d_deg_in[base + t] : 0;
    int x = v;
    #pragma unroll
    for (int o = 1; o < 32; o <<= 1) {
      int y = __shfl_up_sync(0xffffffffu, x, o);
      if (lane >= o) x += y;
    }
    if (lane == 31) warp_tot[w] = x;
    __syncthreads();
    if (w == 0) {
      int y = warp_tot[lane];
      int z = y;
      #pragma unroll
      for (int o = 1; o < 32; o <<= 1) {
        int q = __shfl_up_sync(0xffffffffu, z, o);
        if (lane >= o) z += q;
      }
      warp_tot[lane] = z - y;
    }
    __syncthreads();
    int incl = x + warp_tot[w];
    int carry = s_carry;
    if (base + t < NN) d_rowptr[base + t] = carry + incl - v;
    __syncthreads();
    if (t == 1023) s_carry = carry + incl;
    __syncthreads();
  }
  if (threadIdx.x == 0) d_rowptr[NN] = s_carry;
}

__global__ void k_fill(const int* __restrict__ src, const int* __restrict__ dst) {
  int e = blockIdx.x * blockDim.x + threadIdx.x;
  if (e < EE) {
    int dnode = dst[e];
    int pos = atomicAdd(&d_cursor[dnode], 1);
    int idx = d_rowptr[dnode] + pos;
    d_eid[idx] = e;
    d_esrc[idx] = src[e];
  }
}

__global__ void k_norms() {
  int i = blockIdx.x * blockDim.x + threadIdx.x;
  if (i < NN) {
    int di = d_deg_in[i];
    int dq = d_deg_out[i];
    d_norm_i[i] = (di > 0) ? rsqrtf((float)di) : 0.f;
    d_norm_o[i] = (dq > 0) ? rsqrtf((float)dq) : 0.f;
  }
}

// convert + transpose all 12 weight matrices into fp16 [n][k]
__global__ void k_wcvt(const float* __restrict__ Wc1, const float* __restrict__ Wc2) {
  int i = blockIdx.x * blockDim.x + threadIdx.x;
  if (i >= 12 * 65536) return;
  int slot = i >> 16, r = i & 65535;
  int k = r >> 8, n = r & 255;
  float w = (slot < 6) ? Wc1[(size_t)slot * 65536 + k * 256 + n]
                       : Wc2[(size_t)(slot - 6) * 65536 + k * 256 + n];
  d_wh[(size_t)slot * 65536 + n * 256 + k] = __float2half_rn(w);
}

// ---------------- layer-0 gather ------------------------------------------------
__global__ void __launch_bounds__(256) k_gather0(
    const float* __restrict__ a_t, const float* __restrict__ c_t,
    const float* __restrict__ x_t, const float* __restrict__ e_t) {
  int wid = threadIdx.x >> 5, l = threadIdx.x & 31;
  int n = blockIdx.x * 8 + wid;
  if (n >= NN) return;
  int beg = d_rowptr[n], end = d_rowptr[n + 1];
  float accf = 0.f, acce = 0.f;
  for (int p = beg; p < end; p++) {
    int eid = d_eid[p];
    int s = d_esrc[p];
    float no = d_norm_o[s];
    float f = 0.f;
    if (l < 16) f = a_t[s * 16 + l];
    else if (l < 24) f = c_t[s * 8 + (l - 16)];
    else if (l < 27) f = x_t[s * 3 + (l - 24)];
    accf += f * no;
    if (l < 16) acce += e_t[(size_t)eid * 16 + l];
  }
  int deg = end - beg;
  if (l < 27) d_s0[n * 48 + l] = accf * d_norm_i[n];
  if (l < 16) d_s0[n * 48 + 32 + l] = acce / (float)max(deg, 1);
}

// ---------------- layer 0 (writes fp16 h into d_hn, fp32 into d_hres) -----------
__global__ void __launch_bounds__(256) k_layer0(
    const float* __restrict__ W_in, const float* __restrict__ b_in,
    const float* __restrict__ W_e, const float* __restrict__ b_e) {
  __shared__ float st[16][48];
  int j = threadIdx.x;
  int node0 = blockIdx.x * 16;
  float wf[27], we[16];
  #pragma unroll
  for (int k = 0; k < 27; k++) wf[k] = W_in[k * 256 + j];
  #pragma unroll
  for (int k = 0; k < 16; k++) we[k] = W_e[k * 256 + j];
  for (int q = j; q < 16 * 48; q += 256) {
    int r = q / 48, c = q % 48;
    int nd = node0 + r;
    st[r][c] = (nd < NN) ? d_s0[nd * 48 + c] : 0.f;
  }
  __syncthreads();
  float bi = b_in[j], be = b_e[j];
  for (int rr = 0; rr < 16; rr++) {
    int nd = node0 + rr;
    if (nd >= NN) break;
    float v = bi;
    #pragma unroll
    for (int k = 0; k < 27; k++) v += wf[k] * st[rr][k];
    if (d_deg_in[nd] > 0) {
      float e = be;
      #pragma unroll
      for (int k = 0; k < 16; k++) e += we[k] * st[rr][32 + k];
      v += e;
    }
    d_hn[(size_t)nd * HSTRIDE + j] = __float2half_rn(v);
    d_hres[(size_t)nd * 256 + j] = v;
  }
}

// ---------------- gather: s = norm_i * sum(norm_o[src] * fp16 hn[src]) ----------
__global__ void __launch_bounds__(256) k_gather() {
  __shared__ int ssrc[8][128];
  int wid = threadIdx.x >> 5, l = threadIdx.x & 31;
  int n = blockIdx.x * 8 + wid;
  if (n >= NN) return;
  int beg = d_rowptr[n], end = d_rowptr[n + 1];
  const int gc = l * 8;
  float acc[8];
  #pragma unroll
  for (int c = 0; c < 8; c++) acc[c] = 0.f;
  for (int base = beg; base < end; base += 128) {
    int cnt = min(128, end - base);
    for (int i = l; i < cnt; i += 32) ssrc[wid][i] = d_esrc[base + i];
    __syncwarp();
    int e = 0;
    for (; e + 2 <= cnt; e += 2) {
      int s0 = ssrc[wid][e], s1 = ssrc[wid][e + 1];
      float n0 = d_norm_o[s0], n1 = d_norm_o[s1];
      uint4 a0 = *(const uint4*)(d_hn + (size_t)s0 * HSTRIDE + gc);
      uint4 a1 = *(const uint4*)(d_hn + (size_t)s1 * HSTRIDE + gc);
      const __half2* p0 = (const __half2*)&a0;
      const __half2* p1 = (const __half2*)&a1;
      #pragma unroll
      for (int c = 0; c < 4; c++) {
        float2 f0 = __half22float2(p0[c]);
        float2 f1 = __half22float2(p1[c]);
        acc[2 * c]     += f0.x * n0 + f1.x * n1;
        acc[2 * c + 1] += f0.y * n0 + f1.y * n1;
      }
    }
    if (e < cnt) {
      int s0 = ssrc[wid][e];
      float n0 = d_norm_o[s0];
      uint4 a0 = *(const uint4*)(d_hn + (size_t)s0 * HSTRIDE + gc);
      const __half2* p0 = (const __half2*)&a0;
      #pragma unroll
      for (int c = 0; c < 4; c++) {
        float2 f0 = __half22float2(p0[c]);
        acc[2 * c]     += f0.x * n0;
        acc[2 * c + 1] += f0.y * n0;
      }
    }
    __syncwarp();
  }
  float ni = d_norm_i[n];
  uint4 hv;
  hv.x = h2pack(acc[0] * ni, acc[1] * ni);
  hv.y = h2pack(acc[2] * ni, acc[3] * ni);
  hv.z = h2pack(acc[4] * ni, acc[5] * ni);
  hv.w = h2pack(acc[6] * ni, acc[7] * ni);
  *(uint4*)(d_s + (size_t)n * 256 + gc) = hv;
}

// ---------------- fused GEMM + bias + LN + SiLU + resid + pack ------------------
// block = 64 rows x N=256, 256 threads (8 warps: 2m x 4n), warp tile 32x64.
// BK=32, 3-stage B ring, 2-slab prefetch, SINGLE barrier per slab.
#define A_ROW 528                          // 512B data + 16 pad
#define A_SZ (64 * A_ROW)                  // 33792
#define B_OFF A_SZ
#define B_LROW 64
#define B_STG (256 * B_LROW)               // 16384 per stage
#define FUSED_SMEM (B_OFF + 3 * B_STG)     // 82944 bytes

extern __shared__ __align__(16) unsigned char g_sm[];

__global__ void __launch_bounds__(256, 2) k_fused(
    int wslot, const float* __restrict__ bias, const float* __restrict__ gamma,
    const float* __restrict__ beta, int resid) {
  const __half* wh = d_wh + (size_t)wslot * 65536;

  const int t = threadIdx.x;
  const int lane = t & 31;
  const int wid = t >> 5;
  const int wm = wid & 1;       // 0..1 (m)
  const int wn = wid >> 1;      // 0..3 (n)
  const int fr = lane >> 2;
  const int fc = lane & 3;
  const int bm = blockIdx.x * 64;
  const int sel = lane >> 3;
  const int lr = lane & 7;

  unsigned sbase = (unsigned)__cvta_generic_to_shared((void*)g_sm);

  // ---- A dense load: 64 rows x 32 chunks (16B), zfill OOB rows ----
  #pragma unroll
  for (int i = 0; i < 8; i++) {
    int q = t + 256 * i;
    int r = q >> 5;
    int c = q & 31;
    int gr = bm + r;
    bool ok = gr < NN;
    cpa16(sbase + r * A_ROW + c * 16,
          d_s + (size_t)(ok ? gr : 0) * 256 + c * 8, ok);
  }

  // ---- B stage loader: 256 rows x 64B (K32 slab), swizzled ----
  auto load_b = [&](int st, int k0) {
    unsigned sb = sbase + B_OFF + st * B_STG;
    #pragma unroll
    for (int i2 = 0; i2 < 4; i2++) {
      int q = t + 256 * i2;             // 1024: 256 rows x 4 chunks
      int row = q >> 2, c = q & 3;
      unsigned off = row * B_LROW + ((c ^ ((row >> 1) & 3)) << 4);
      cpa16(sb + off, wh + (size_t)row * 256 + k0 + c * 8, true);
    }
    cpa_commit();
  };
  load_b(0, 0);     // commits A + B0 together
  load_b(1, 32);

  // ---- MMA mainloop (8 K32 slabs), single barrier per slab ----
  float acc[2][8][4];
  #pragma unroll
  for (int i = 0; i < 2; i++)
    #pragma unroll
    for (int j = 0; j < 8; j++)
      #pragma unroll
      for (int q = 0; q < 4; q++) acc[i][j][q] = 0.f;

  const int a_row = (sel & 1) * 8 + lr;
  const int a_kad = (sel >> 1) * 8;
  const int b_row = (sel >> 1) * 8 + lr;
  const int b_kc  = sel & 1;

  #pragma unroll 1
  for (int s = 0; s < 8; s++) {
    if (s == 7) cpa_wait<0>(); else cpa_wait<1>();
    __syncthreads();
    // prefetch slab s+2 into stage (s+2)%3: that stage was consumed at slab
    // s-1 and the barrier above guarantees all warps have passed it.
    if (s + 2 < 8) load_b((s + 2) % 3, (s + 2) * 32);

    unsigned sb = sbase + B_OFF + (s % 3) * B_STG;
    const int ka = s * 32;
    #pragma unroll
    for (int kt = 0; kt < 2; kt++) {
      const int kb = kt * 16;
      unsigned af[2][4];
      #pragma unroll
      for (int i = 0; i < 2; i++) {
        int row = wm * 32 + i * 16 + a_row;
        ldsm4(af[i], sbase + row * A_ROW + (ka + kb + a_kad) * 2);
      }
      unsigned bf[4][4];
      const int cidx = kt * 2 + b_kc;
      #pragma unroll
      for (int g = 0; g < 4; g++) {
        int nrow = wn * 64 + g * 16 + b_row;
        ldsm4(bf[g], sb + nrow * B_LROW + ((cidx ^ ((nrow >> 1) & 3)) << 4));
      }
      #pragma unroll
      for (int i = 0; i < 2; i++)
        #pragma unroll
        for (int g = 0; g < 4; g++) {
          mma_f16(acc[i][2 * g],     af[i], bf[g]);
          mma_f16(acc[i][2 * g + 1], af[i], bf[g] + 2);
        }
    }
  }

  // ---- epilogue: bias -> LN -> SiLU -> resid -> pack ----
  __syncthreads();
  float* epi = (float*)g_sm;
  float* psum = epi;              // [64][4]
  float* psq  = epi + 256;        // [64][4]
  float* pmu  = epi + 512;        // [64]
  float* prs  = epi + 576;        // [64]

  #pragma unroll
  for (int j = 0; j < 8; j++) {
    int c0 = wn * 64 + j * 8 + 2 * fc;
    float b0 = bias[c0], b1 = bias[c0 + 1];
    #pragma unroll
    for (int i = 0; i < 2; i++) {
      acc[i][j][0] += b0; acc[i][j][1] += b1;
      acc[i][j][2] += b0; acc[i][j][3] += b1;
    }
  }

  #pragma unroll
  for (int i = 0; i < 2; i++) {
    float s0 = 0.f, q0 = 0.f, s1 = 0.f, q1 = 0.f;
    #pragma unroll
    for (int j = 0; j < 8; j++) {
      s0 += acc[i][j][0] + acc[i][j][1];
      q0 += acc[i][j][0] * acc[i][j][0] + acc[i][j][1] * acc[i][j][1];
      s1 += acc[i][j][2] + acc[i][j][3];
      q1 += acc[i][j][2] * acc[i][j][2] + acc[i][j][3] * acc[i][j][3];
    }
    #pragma unroll
    for (int o = 1; o <= 2; o <<= 1) {
      s0 += __shfl_xor_sync(0xffffffffu, s0, o);
      q0 += __shfl_xor_sync(0xffffffffu, q0, o);
      s1 += __shfl_xor_sync(0xffffffffu, s1, o);
      q1 += __shfl_xor_sync(0xffffffffu, q1, o);
    }
    if (fc == 0) {
      int r0 = wm * 32 + i * 16 + fr;
      psum[r0 * 4 + wn] = s0; psq[r0 * 4 + wn] = q0;
      psum[(r0 + 8) * 4 + wn] = s1; psq[(r0 + 8) * 4 + wn] = q1;
    }
  }
  __syncthreads();
  if (t < 64) {
    float s = psum[t * 4] + psum[t * 4 + 1] + psum[t * 4 + 2] + psum[t * 4 + 3];
    float q = psq[t * 4] + psq[t * 4 + 1] + psq[t * 4 + 2] + psq[t * 4 + 3];
    float mu = s * (1.f / 256.f);
    float var = q * (1.f / 256.f) - mu * mu;
    pmu[t] = mu;
    prs[t] = rsqrtf(var + 1e-5f);
  }
  __syncthreads();

  #pragma unroll
  for (int i = 0; i < 2; i++) {
    int r0l = wm * 32 + i * 16 + fr;
    int r1l = r0l + 8;
    int gr0 = bm + r0l, gr1 = bm + r1l;
    float mu0 = pmu[r0l], rs0 = prs[r0l];
    float mu1 = pmu[r1l], rs1 = prs[r1l];
    #pragma unroll
    for (int j = 0; j < 8; j++) {
      int c0 = wn * 64 + j * 8 + 2 * fc;
      float ga0 = gamma[c0], ga1 = gamma[c0 + 1];
      float be0 = beta[c0], be1 = beta[c0 + 1];
      float y0 = (acc[i][j][0] - mu0) * rs0 * ga0 + be0;
      float y1 = (acc[i][j][1] - mu0) * rs0 * ga1 + be1;
      float y2 = (acc[i][j][2] - mu1) * rs1 * ga0 + be0;
      float y3 = (acc[i][j][3] - mu1) * rs1 * ga1 + be1;
      y0 = __fdividef(y0, 1.f + __expf(-y0));
      y1 = __fdividef(y1, 1.f + __expf(-y1));
      y2 = __fdividef(y2, 1.f + __expf(-y2));
      y3 = __fdividef(y3, 1.f + __expf(-y3));
      if (gr0 < NN) {
        if (resid) {
          size_t rx = (size_t)gr0 * 256 + c0;
          float2 old = *(float2*)(d_hres + rx);
          y0 += old.x; y1 += old.y;
          *(float2*)(d_hres + rx) = make_float2(y0, y1);
        }
        *(unsigned*)(d_hn + (size_t)gr0 * HSTRIDE + c0) = h2pack(y0, y1);
      }
      if (gr1 < NN) {
        if (resid) {
          size_t rx = (size_t)gr1 * 256 + c0;
          float2 old = *(float2*)(d_hres + rx);
          y2 += old.x; y3 += old.y;
          *(float2*)(d_hres + rx) = make_float2(y2, y3);
        }
        *(unsigned*)(d_hn + (size_t)gr1 * HSTRIDE + c0) = h2pack(y2, y3);
      }
    }
  }
}

// ---------------- fused pool + head (graph_id sorted -> no atomics) -------------
__global__ void __launch_bounds__(256) k_poolhead(
    const int* __restrict__ gid, const float* __restrict__ W_head,
    const float* __restrict__ b_head, float* __restrict__ out) {
  __shared__ float red[8];
  int g = blockIdx.x, j = threadIdx.x;
  int lo = 0, hi = NN;
  while (lo < hi) { int m = (lo + hi) >> 1; if (gid[m] < g) lo = m + 1; else hi = m; }
  int lo2 = lo, hi2 = NN;
  while (lo2 < hi2) { int m = (lo2 + hi2) >> 1; if (gid[m] < g + 1) lo2 = m + 1; else hi2 = m; }
  float sum = 0.f;
  for (int n = lo; n < lo2; n++)
    sum += d_hres[(size_t)n * 256 + j];
  float cnt = (float)(lo2 - lo);
  float v = sum / fmaxf(cnt, 1.f) * W_head[j];
  float s = block_sum_256(v, red);
  if (j == 0) {
    float x = s + b_head[0];
    out[g] = (x > 20.f) ? x : log1pf(expf(x));
  }
}

// ---------------- launcher ------------------------------------------------------
extern "C" void kernel_launch(void* const* d_in, const int* in_sizes, int n_in,
                              void* d_out, int out_size) {
  const float* a_t   = (const float*)d_in[0];
  const float* c_t   = (const float*)d_in[1];
  const float* x_t   = (const float*)d_in[2];
  const float* e_t   = (const float*)d_in[3];
  const int*   src   = (const int*)d_in[4];
  const int*   dst   = (const int*)d_in[5];
  const int*   gid   = (const int*)d_in[6];
  const float* W_in  = (const float*)d_in[7];
  const float* b_in  = (const float*)d_in[8];
  const float* W_e   = (const float*)d_in[9];
  const float* b_e   = (const float*)d_in[10];
  const float* Wc1   = (const float*)d_in[11];
  const float* bc1   = (const float*)d_in[12];
  const float* g1    = (const float*)d_in[13];
  const float* be1   = (const float*)d_in[14];
  const float* Wc2   = (const float*)d_in[15];
  const float* bc2   = (const float*)d_in[16];
  const float* g2    = (const float*)d_in[17];
  const float* be2   = (const float*)d_in[18];
  const float* W_hd  = (const float*)d_in[19];
  const float* b_hd  = (const float*)d_in[20];
  float* out = (float*)d_out;

  static bool attr_set = false;
  if (!attr_set) {
    cudaFuncSetAttribute(k_fused, cudaFuncAttributeMaxDynamicSharedMemorySize,
                         FUSED_SMEM);
    attr_set = true;
  }

  const int FGRID = (NN + 63) / 64;   // 782

  k_zero<<<(NN + 255) / 256, 256>>>();
  k_hist<<<(EE + 255) / 256, 256>>>(src, dst);
  k_scan<<<1, 1024>>>();
  k_fill<<<(EE + 255) / 256, 256>>>(src, dst);
  k_norms<<<(NN + 255) / 256, 256>>>();
  k_wcvt<<<(12 * 65536 + 255) / 256, 256>>>(Wc1, Wc2);

  k_gather0<<<(NN + 7) / 8, 256>>>(a_t, c_t, x_t, e_t);
  k_layer0<<<(NN + 15) / 16, 256>>>(W_in, b_in, W_e, b_e);

  for (int l = 0; l < NDEPTH; l++) {
    k_gather<<<(NN + 7) / 8, 256>>>();
    k_fused<<<FGRID, 256, FUSED_SMEM>>>(l, bc1 + l * HH, g1 + l * HH,
                                        be1 + l * HH, 0);
    k_gather<<<(NN + 7) / 8, 256>>>();
    k_fused<<<FGRID, 256, FUSED_SMEM>>>(6 + l, bc2 + l * HH, g2 + l * HH,
                                        be2 + l * HH, 1);
  }

  k_poolhead<<<GG, 256>>>(gid, W_hd, b_hd, out);
}

// round 17
// speedup vs baseline: 2.5520x; 1.0769x over previous
#include <cuda_runtime.h>
#include <cuda_bf16.h>
#include <cuda_fp16.h>
#include <math.h>

#define NN 50000
#define EE 400000
#define GG 256
#define HH 256
#define NDEPTH 6
#define HSTRIDE 512   // fp16 elements per d_hn row (512B data + 512B pad = 1024B)

// ---------------- scratch (device globals) -----------------------------------
__device__ __half d_hn[(size_t)NN * HSTRIDE];  // fp16 message value (gather input)
__device__ __half d_hr[NN * HH];               // fp16 residual state (dense)
__device__ __half d_s[NN * HH];                // gathered sums, fp16 (GEMM A)
__device__ float d_s0[NN * 48];                // layer-0 gathered feats/edge means
__device__ __half d_wh[12 * HH * HH];          // weights transposed [n][k], fp16
__device__ int   d_deg_in[NN];
__device__ int   d_deg_out[NN];
__device__ int   d_cursor[NN];
__device__ int   d_rowptr[NN + 1];
__device__ int   d_eid[EE];
__device__ int   d_esrc[EE];
__device__ float d_norm_o[NN];
__device__ float d_norm_i[NN];

// ---------------- helpers -----------------------------------------------------
__device__ __forceinline__ float block_sum_256(float v, float* red) {
  #pragma unroll
  for (int o = 16; o > 0; o >>= 1) v += __shfl_down_sync(0xffffffffu, v, o);
  int lane = threadIdx.x & 31, w = threadIdx.x >> 5;
  if (lane == 0) red[w] = v;
  __syncthreads();
  if (threadIdx.x < 8) {
    float x = red[threadIdx.x];
    #pragma unroll
    for (int o = 4; o > 0; o >>= 1) x += __shfl_down_sync(0xffu, x, o);
    if (threadIdx.x == 0) red[0] = x;
  }
  __syncthreads();
  float r = red[0];
  __syncthreads();
  return r;
}

__device__ __forceinline__ unsigned h2pack(float a, float b) {
  return (unsigned)__half_as_ushort(__float2half_rn(a)) |
         ((unsigned)__half_as_ushort(__float2half_rn(b)) << 16);
}

__device__ __forceinline__ void mma_f16(float* c, const unsigned* a, const unsigned* b) {
  asm volatile(
      "mma.sync.aligned.m16n8k16.row.col.f32.f16.f16.f32 "
      "{%0,%1,%2,%3}, {%4,%5,%6,%7}, {%8,%9}, {%0,%1,%2,%3};\n"
      : "+f"(c[0]), "+f"(c[1]), "+f"(c[2]), "+f"(c[3])
      : "r"(a[0]), "r"(a[1]), "r"(a[2]), "r"(a[3]), "r"(b[0]), "r"(b[1]));
}

__device__ __forceinline__ void ldsm4(unsigned* r, unsigned saddr) {
  asm volatile("ldmatrix.sync.aligned.m8n8.x4.shared.b16 {%0,%1,%2,%3}, [%4];"
               : "=r"(r[0]), "=r"(r[1]), "=r"(r[2]), "=r"(r[3]) : "r"(saddr));
}

__device__ __forceinline__ void cpa16(unsigned saddr, const void* gaddr, bool pred) {
  int sz = pred ? 16 : 0;
  asm volatile("cp.async.cg.shared.global [%0], [%1], 16, %2;\n"
               :: "r"(saddr), "l"(gaddr), "r"(sz));
}
__device__ __forceinline__ void cpa_commit() {
  asm volatile("cp.async.commit_group;\n");
}
template <int N>
__device__ __forceinline__ void cpa_wait() {
  asm volatile("cp.async.wait_group %0;\n" :: "n"(N));
}

// ---------------- preprocessing -----------------------------------------------
__global__ void k_zero() {
  int i = blockIdx.x * blockDim.x + threadIdx.x;
  if (i < NN) { d_deg_in[i] = 0; d_deg_out[i] = 0; d_cursor[i] = 0; }
}

__global__ void k_hist(const int* __restrict__ src, const int* __restrict__ dst) {
  int e = blockIdx.x * blockDim.x + threadIdx.x;
  if (e < EE) {
    atomicAdd(&d_deg_in[dst[e]], 1);
    atomicAdd(&d_deg_out[src[e]], 1);
  }
}

// exclusive scan of deg_in -> rowptr; also computes norms (deg arrays intact)
__global__ void k_scan() {
  __shared__ int warp_tot[32];
  __shared__ int s_carry;
  int t = threadIdx.x, lane = t & 31, w = t >> 5;
  if (t == 0) s_carry = 0;
  __syncthreads();
  for (int base = 0; base < NN; base += 1024) {
    int v = (base + t < NN) ? d_deg_in[base + t] : 0;
    int x = v;
    #pragma unroll
    for (int o = 1; o < 32; o <<= 1) {
      int y = __shfl_up_sync(0xffffffffu, x, o);
      if (lane >= o) x += y;
    }
    if (lane == 31) warp_tot[w] = x;
    __syncthreads();
    if (w == 0) {
      int y = warp_tot[lane];
      int z = y;
      #pragma unroll
      for (int o = 1; o < 32; o <<= 1) {
        int q = __shfl_up_sync(0xffffffffu, z, o);
        if (lane >= o) z += q;
      }
      warp_tot[lane] = z - y;
    }
    __syncthreads();
    int incl = x + warp_tot[w];
    int carry = s_carry;
    if (base + t < NN) d_rowptr[base + t] = carry + incl - v;
    __syncthreads();
    if (t == 1023) s_carry = carry + incl;
    __syncthreads();
  }
  if (threadIdx.x == 0) d_rowptr[NN] = s_carry;
  for (int i = t; i < NN; i += 1024) {
    int di = d_deg_in[i];
    int dq = d_deg_out[i];
    d_norm_i[i] = (di > 0) ? rsqrtf((float)di) : 0.f;
    d_norm_o[i] = (dq > 0) ? rsqrtf((float)dq) : 0.f;
  }
}

__global__ void k_fill(const int* __restrict__ src, const int* __restrict__ dst) {
  int e = blockIdx.x * blockDim.x + threadIdx.x;
  if (e < EE) {
    int dnode = dst[e];
    int pos = atomicAdd(&d_cursor[dnode], 1);
    int idx = d_rowptr[dnode] + pos;
    d_eid[idx] = e;
    d_esrc[idx] = src[e];
  }
}

// convert + transpose all 12 weight matrices into fp16 [n][k]
__global__ void k_wcvt(const float* __restrict__ Wc1, const float* __restrict__ Wc2) {
  int i = blockIdx.x * blockDim.x + threadIdx.x;
  if (i >= 12 * 65536) return;
  int slot = i >> 16, r = i & 65535;
  int k = r >> 8, n = r & 255;
  float w = (slot < 6) ? Wc1[(size_t)slot * 65536 + k * 256 + n]
                       : Wc2[(size_t)(slot - 6) * 65536 + k * 256 + n];
  d_wh[(size_t)slot * 65536 + n * 256 + k] = __float2half_rn(w);
}

// ---------------- layer-0 gather ------------------------------------------------
__global__ void __launch_bounds__(256) k_gather0(
    const float* __restrict__ a_t, const float* __restrict__ c_t,
    const float* __restrict__ x_t, const float* __restrict__ e_t) {
  int wid = threadIdx.x >> 5, l = threadIdx.x & 31;
  int n = blockIdx.x * 8 + wid;
  if (n >= NN) return;
  int beg = d_rowptr[n], end = d_rowptr[n + 1];
  float accf = 0.f, acce = 0.f;
  for (int p = beg; p < end; p++) {
    int eid = d_eid[p];
    int s = d_esrc[p];
    float no = d_norm_o[s];
    float f = 0.f;
    if (l < 16) f = a_t[s * 16 + l];
    else if (l < 24) f = c_t[s * 8 + (l - 16)];
    else if (l < 27) f = x_t[s * 3 + (l - 24)];
    accf += f * no;
    if (l < 16) acce += e_t[(size_t)eid * 16 + l];
  }
  int deg = end - beg;
  if (l < 27) d_s0[n * 48 + l] = accf * d_norm_i[n];
  if (l < 16) d_s0[n * 48 + 32 + l] = acce / (float)max(deg, 1);
}

// ---------------- layer 0 (writes fp16 h into d_hn and d_hr) --------------------
__global__ void __launch_bounds__(256) k_layer0(
    const float* __restrict__ W_in, const float* __restrict__ b_in,
    const float* __restrict__ W_e, const float* __restrict__ b_e) {
  __shared__ float st[16][48];
  int j = threadIdx.x;
  int node0 = blockIdx.x * 16;
  float wf[27], we[16];
  #pragma unroll
  for (int k = 0; k < 27; k++) wf[k] = W_in[k * 256 + j];
  #pragma unroll
  for (int k = 0; k < 16; k++) we[k] = W_e[k * 256 + j];
  for (int q = j; q < 16 * 48; q += 256) {
    int r = q / 48, c = q % 48;
    int nd = node0 + r;
    st[r][c] = (nd < NN) ? d_s0[nd * 48 + c] : 0.f;
  }
  __syncthreads();
  float bi = b_in[j], be = b_e[j];
  for (int rr = 0; rr < 16; rr++) {
    int nd = node0 + rr;
    if (nd >= NN) break;
    float v = bi;
    #pragma unroll
    for (int k = 0; k < 27; k++) v += wf[k] * st[rr][k];
    if (d_deg_in[nd] > 0) {
      float e = be;
      #pragma unroll
      for (int k = 0; k < 16; k++) e += we[k] * st[rr][32 + k];
      v += e;
    }
    __half hv = __float2half_rn(v);
    d_hn[(size_t)nd * HSTRIDE + j] = hv;
    d_hr[(size_t)nd * 256 + j] = hv;
  }
}

// ---------------- gather: s = norm_i * sum(norm_o[src] * fp16 hn[src]) ----------
__global__ void __launch_bounds__(256) k_gather() {
  __shared__ int ssrc[8][128];
  int wid = threadIdx.x >> 5, l = threadIdx.x & 31;
  int n = blockIdx.x * 8 + wid;
  if (n >= NN) return;
  int beg = d_rowptr[n], end = d_rowptr[n + 1];
  const int gc = l * 8;
  float acc[8];
  #pragma unroll
  for (int c = 0; c < 8; c++) acc[c] = 0.f;
  for (int base = beg; base < end; base += 128) {
    int cnt = min(128, end - base);
    for (int i = l; i < cnt; i += 32) ssrc[wid][i] = d_esrc[base + i];
    __syncwarp();
    int e = 0;
    for (; e + 2 <= cnt; e += 2) {
      int s0 = ssrc[wid][e], s1 = ssrc[wid][e + 1];
      float n0 = d_norm_o[s0], n1 = d_norm_o[s1];
      uint4 a0 = *(const uint4*)(d_hn + (size_t)s0 * HSTRIDE + gc);
      uint4 a1 = *(const uint4*)(d_hn + (size_t)s1 * HSTRIDE + gc);
      const __half2* p0 = (const __half2*)&a0;
      const __half2* p1 = (const __half2*)&a1;
      #pragma unroll
      for (int c = 0; c < 4; c++) {
        float2 f0 = __half22float2(p0[c]);
        float2 f1 = __half22float2(p1[c]);
        acc[2 * c]     += f0.x * n0 + f1.x * n1;
        acc[2 * c + 1] += f0.y * n0 + f1.y * n1;
      }
    }
    if (e < cnt) {
      int s0 = ssrc[wid][e];
      float n0 = d_norm_o[s0];
      uint4 a0 = *(const uint4*)(d_hn + (size_t)s0 * HSTRIDE + gc);
      const __half2* p0 = (const __half2*)&a0;
      #pragma unroll
      for (int c = 0; c < 4; c++) {
        float2 f0 = __half22float2(p0[c]);
        acc[2 * c]     += f0.x * n0;
        acc[2 * c + 1] += f0.y * n0;
      }
    }
    __syncwarp();
  }
  float ni = d_norm_i[n];
  uint4 hv;
  hv.x = h2pack(acc[0] * ni, acc[1] * ni);
  hv.y = h2pack(acc[2] * ni, acc[3] * ni);
  hv.z = h2pack(acc[4] * ni, acc[5] * ni);
  hv.w = h2pack(acc[6] * ni, acc[7] * ni);
  *(uint4*)(d_s + (size_t)n * 256 + gc) = hv;
}

// ---------------- fused GEMM + bias + LN + SiLU + resid + pack ------------------
// block = 64 rows x N=256, 256 threads (8 warps: 2m x 4n), warp tile 32x64.
// BK=32, 3-stage B ring, 2-slab prefetch, single barrier per slab.
#define A_ROW 528                          // 512B data + 16 pad
#define A_SZ (64 * A_ROW)                  // 33792
#define B_OFF A_SZ
#define B_LROW 64
#define B_STG (256 * B_LROW)               // 16384 per stage
#define FUSED_SMEM (B_OFF + 3 * B_STG)     // 82944 bytes

extern __shared__ __align__(16) unsigned char g_sm[];

__global__ void __launch_bounds__(256, 2) k_fused(
    int wslot, const float* __restrict__ bias, const float* __restrict__ gamma,
    const float* __restrict__ beta, int resid) {
  const __half* wh = d_wh + (size_t)wslot * 65536;

  const int t = threadIdx.x;
  const int lane = t & 31;
  const int wid = t >> 5;
  const int wm = wid & 1;       // 0..1 (m)
  const int wn = wid >> 1;      // 0..3 (n)
  const int fr = lane >> 2;
  const int fc = lane & 3;
  const int bm = blockIdx.x * 64;
  const int sel = lane >> 3;
  const int lr = lane & 7;

  unsigned sbase = (unsigned)__cvta_generic_to_shared((void*)g_sm);

  // ---- A dense load: 64 rows x 32 chunks (16B), zfill OOB rows ----
  #pragma unroll
  for (int i = 0; i < 8; i++) {
    int q = t + 256 * i;
    int r = q >> 5;
    int c = q & 31;
    int gr = bm + r;
    bool ok = gr < NN;
    cpa16(sbase + r * A_ROW + c * 16,
          d_s + (size_t)(ok ? gr : 0) * 256 + c * 8, ok);
  }

  // ---- B stage loader: 256 rows x 64B (K32 slab), swizzled ----
  auto load_b = [&](int st, int k0) {
    unsigned sb = sbase + B_OFF + st * B_STG;
    #pragma unroll
    for (int i2 = 0; i2 < 4; i2++) {
      int q = t + 256 * i2;             // 1024: 256 rows x 4 chunks
      int row = q >> 2, c = q & 3;
      unsigned off = row * B_LROW + ((c ^ ((row >> 1) & 3)) << 4);
      cpa16(sb + off, wh + (size_t)row * 256 + k0 + c * 8, true);
    }
    cpa_commit();
  };
  load_b(0, 0);     // commits A + B0 together
  load_b(1, 32);

  // ---- MMA mainloop (8 K32 slabs), single barrier per slab ----
  float acc[2][8][4];
  #pragma unroll
  for (int i = 0; i < 2; i++)
    #pragma unroll
    for (int j = 0; j < 8; j++)
      #pragma unroll
      for (int q = 0; q < 4; q++) acc[i][j][q] = 0.f;

  const int a_row = (sel & 1) * 8 + lr;
  const int a_kad = (sel >> 1) * 8;
  const int b_row = (sel >> 1) * 8 + lr;
  const int b_kc  = sel & 1;

  #pragma unroll 1
  for (int s = 0; s < 8; s++) {
    if (s == 7) cpa_wait<0>(); else cpa_wait<1>();
    __syncthreads();
    if (s + 2 < 8) load_b((s + 2) % 3, (s + 2) * 32);

    unsigned sb = sbase + B_OFF + (s % 3) * B_STG;
    const int ka = s * 32;
    #pragma unroll
    for (int kt = 0; kt < 2; kt++) {
      const int kb = kt * 16;
      unsigned af[2][4];
      #pragma unroll
      for (int i = 0; i < 2; i++) {
        int row = wm * 32 + i * 16 + a_row;
        ldsm4(af[i], sbase + row * A_ROW + (ka + kb + a_kad) * 2);
      }
      unsigned bf[4][4];
      const int cidx = kt * 2 + b_kc;
      #pragma unroll
      for (int g = 0; g < 4; g++) {
        int nrow = wn * 64 + g * 16 + b_row;
        ldsm4(bf[g], sb + nrow * B_LROW + ((cidx ^ ((nrow >> 1) & 3)) << 4));
      }
      #pragma unroll
      for (int i = 0; i < 2; i++)
        #pragma unroll
        for (int g = 0; g < 4; g++) {
          mma_f16(acc[i][2 * g],     af[i], bf[g]);
          mma_f16(acc[i][2 * g + 1], af[i], bf[g] + 2);
        }
    }
  }

  // ---- epilogue: bias -> LN -> SiLU -> resid -> pack ----
  __syncthreads();
  float* epi = (float*)g_sm;
  float* psum = epi;              // [64][4]
  float* psq  = epi + 256;        // [64][4]
  float* pmu  = epi + 512;        // [64]
  float* prs  = epi + 576;        // [64]

  #pragma unroll
  for (int j = 0; j < 8; j++) {
    int c0 = wn * 64 + j * 8 + 2 * fc;
    float b0 = bias[c0], b1 = bias[c0 + 1];
    #pragma unroll
    for (int i = 0; i < 2; i++) {
      acc[i][j][0] += b0; acc[i][j][1] += b1;
      acc[i][j][2] += b0; acc[i][j][3] += b1;
    }
  }

  #pragma unroll
  for (int i = 0; i < 2; i++) {
    float s0 = 0.f, q0 = 0.f, s1 = 0.f, q1 = 0.f;
    #pragma unroll
    for (int j = 0; j < 8; j++) {
      s0 += acc[i][j][0] + acc[i][j][1];
      q0 += acc[i][j][0] * acc[i][j][0] + acc[i][j][1] * acc[i][j][1];
      s1 += acc[i][j][2] + acc[i][j][3];
      q1 += acc[i][j][2] * acc[i][j][2] + acc[i][j][3] * acc[i][j][3];
    }
    #pragma unroll
    for (int o = 1; o <= 2; o <<= 1) {
      s0 += __shfl_xor_sync(0xffffffffu, s0, o);
      q0 += __shfl_xor_sync(0xffffffffu, q0, o);
      s1 += __shfl_xor_sync(0xffffffffu, s1, o);
      q1 += __shfl_xor_sync(0xffffffffu, q1, o);
    }
    if (fc == 0) {
      int r0 = wm * 32 + i * 16 + fr;
      psum[r0 * 4 + wn] = s0; psq[r0 * 4 + wn] = q0;
      psum[(r0 + 8) * 4 + wn] = s1; psq[(r0 + 8) * 4 + wn] = q1;
    }
  }
  __syncthreads();
  if (t < 64) {
    float s = psum[t * 4] + psum[t * 4 + 1] + psum[t * 4 + 2] + psum[t * 4 + 3];
    float q = psq[t * 4] + psq[t * 4 + 1] + psq[t * 4 + 2] + psq[t * 4 + 3];
    float mu = s * (1.f / 256.f);
    float var = q * (1.f / 256.f) - mu * mu;
    pmu[t] = mu;
    prs[t] = rsqrtf(var + 1e-5f);
  }
  __syncthreads();

  #pragma unroll
  for (int i = 0; i < 2; i++) {
    int r0l = wm * 32 + i * 16 + fr;
    int r1l = r0l + 8;
    int gr0 = bm + r0l, gr1 = bm + r1l;
    float mu0 = pmu[r0l], rs0 = prs[r0l];
    float mu1 = pmu[r1l], rs1 = prs[r1l];
    #pragma unroll
    for (int j = 0; j < 8; j++) {
      int c0 = wn * 64 + j * 8 + 2 * fc;
      float ga0 = gamma[c0], ga1 = gamma[c0 + 1];
      float be0 = beta[c0], be1 = beta[c0 + 1];
      float y0 = (acc[i][j][0] - mu0) * rs0 * ga0 + be0;
      float y1 = (acc[i][j][1] - mu0) * rs0 * ga1 + be1;
      float y2 = (acc[i][j][2] - mu1) * rs1 * ga0 + be0;
      float y3 = (acc[i][j][3] - mu1) * rs1 * ga1 + be1;
      y0 = __fdividef(y0, 1.f + __expf(-y0));
      y1 = __fdividef(y1, 1.f + __expf(-y1));
      y2 = __fdividef(y2, 1.f + __expf(-y2));
      y3 = __fdividef(y3, 1.f + __expf(-y3));
      if (gr0 < NN) {
        if (resid) {
          size_t rx = (size_t)gr0 * 256 + c0;
          float2 old = __half22float2(*(const __half2*)(d_hr + rx));
          y0 += old.x; y1 += old.y;
          *(unsigned*)(d_hr + rx) = h2pack(y0, y1);
        }
        *(unsigned*)(d_hn + (size_t)gr0 * HSTRIDE + c0) = h2pack(y0, y1);
      }
      if (gr1 < NN) {
        if (resid) {
          size_t rx = (size_t)gr1 * 256 + c0;
          float2 old = __half22float2(*(const __half2*)(d_hr + rx));
          y2 += old.x; y3 += old.y;
          *(unsigned*)(d_hr + rx) = h2pack(y2, y3);
        }
        *(unsigned*)(d_hn + (size_t)gr1 * HSTRIDE + c0) = h2pack(y2, y3);
      }
    }
  }
}

// ---------------- fused pool + head (graph_id sorted -> no atomics) -------------
__global__ void __launch_bounds__(256) k_poolhead(
    const int* __restrict__ gid, const float* __restrict__ W_head,
    const float* __restrict__ b_head, float* __restrict__ out) {
  __shared__ float red[8];
  int g = blockIdx.x, j = threadIdx.x;
  int lo = 0, hi = NN;
  while (lo < hi) { int m = (lo + hi) >> 1; if (gid[m] < g) lo = m + 1; else hi = m; }
  int lo2 = lo, hi2 = NN;
  while (lo2 < hi2) { int m = (lo2 + hi2) >> 1; if (gid[m] < g + 1) lo2 = m + 1; else hi2 = m; }
  float sum = 0.f;
  for (int n = lo; n < lo2; n++)
    sum += __half2float(d_hr[(size_t)n * 256 + j]);
  float cnt = (float)(lo2 - lo);
  float v = sum / fmaxf(cnt, 1.f) * W_head[j];
  float s = block_sum_256(v, red);
  if (j == 0) {
    float x = s + b_head[0];
    out[g] = (x > 20.f) ? x : log1pf(expf(x));
  }
}

// ---------------- launcher ------------------------------------------------------
extern "C" void kernel_launch(void* const* d_in, const int* in_sizes, int n_in,
                              void* d_out, int out_size) {
  const float* a_t   = (const float*)d_in[0];
  const float* c_t   = (const float*)d_in[1];
  const float* x_t   = (const float*)d_in[2];
  const float* e_t   = (const float*)d_in[3];
  const int*   src   = (const int*)d_in[4];
  const int*   dst   = (const int*)d_in[5];
  const int*   gid   = (const int*)d_in[6];
  const float* W_in  = (const float*)d_in[7];
  const float* b_in  = (const float*)d_in[8];
  const float* W_e   = (const float*)d_in[9];
  const float* b_e   = (const float*)d_in[10];
  const float* Wc1   = (const float*)d_in[11];
  const float* bc1   = (const float*)d_in[12];
  const float* g1    = (const float*)d_in[13];
  const float* be1   = (const float*)d_in[14];
  const float* Wc2   = (const float*)d_in[15];
  const float* bc2   = (const float*)d_in[16];
  const float* g2    = (const float*)d_in[17];
  const float* be2   = (const float*)d_in[18];
  const float* W_hd  = (const float*)d_in[19];
  const float* b_hd  = (const float*)d_in[20];
  float* out = (float*)d_out;

  static bool attr_set = false;
  if (!attr_set) {
    cudaFuncSetAttribute(k_fused, cudaFuncAttributeMaxDynamicSharedMemorySize,
                         FUSED_SMEM);
    attr_set = true;
  }

  const int FGRID = (NN + 63) / 64;   // 782

  k_zero<<<(NN + 255) / 256, 256>>>();
  k_hist<<<(EE + 255) / 256, 256>>>(src, dst);
  k_scan<<<1, 1024>>>();
  k_fill<<<(EE + 255) / 256, 256>>>(src, dst);
  k_wcvt<<<(12 * 65536 + 255) / 256, 256>>>(Wc1, Wc2);

  k_gather0<<<(NN + 7) / 8, 256>>>(a_t, c_t, x_t, e_t);
  k_layer0<<<(NN + 15) / 16, 256>>>(W_in, b_in, W_e, b_e);

  for (int l = 0; l < NDEPTH; l++) {
    k_gather<<<(NN + 7) / 8, 256>>>();
    k_fused<<<FGRID, 256, FUSED_SMEM>>>(l, bc1 + l * HH, g1 + l * HH,
                                        be1 + l * HH, 0);
    k_gather<<<(NN + 7) / 8, 256>>>();
    k_fused<<<FGRID, 256, FUSED_SMEM>>>(6 + l, bc2 + l * HH, g2 + l * HH,
                                        be2 + l * HH, 1);
  }

  k_poolhead<<<GG, 256>>>(gid, W_hd, b_hd, out);
}